// round 14
// baseline (speedup 1.0000x reference)
#include <cuda_runtime.h>
#include <cuda_bf16.h>
#include <math.h>
#include <stdint.h>

#define Bv 4
#define Sv 1024
#define Dv 1024
#define Hv 16
#define Lv 12
#define Cv 8192
#define FFv 4096
#define HDv 64
#define Mv (Bv*Sv)
#define PADTOK 2
#define QKVS (3*Dv)

// ---------------- scratch ----------------------------------------------------
__device__ float g_x[Mv*Dv];
__device__ __nv_bfloat16 g_h[Mv*Dv];
__device__ __nv_bfloat16 g_qkv[(size_t)Mv*QKVS];
__device__ __nv_bfloat16 g_y[Mv*Dv];
__device__ __nv_bfloat16 g_ff[(size_t)Mv*FFv];
__device__ __nv_bfloat16 g_logits[(size_t)Mv*Cv];

__device__ __nv_bfloat16 g_Wqkv[(size_t)Lv*QKVS*Dv];
__device__ float         g_bqkv[(size_t)Lv*QKVS];
__device__ __nv_bfloat16 g_Wo[(size_t)Lv*Dv*Dv];
__device__ __nv_bfloat16 g_W1[(size_t)Lv*FFv*Dv];
__device__ __nv_bfloat16 g_W2[(size_t)Lv*Dv*FFv];
__device__ __nv_bfloat16 g_fcW[(size_t)Cv*Dv];

// ---------------- fused weight conversion + bias packing ----------------------
#define CW  3145728ULL
#define CFF 12582912ULL
#define CFC 2097152ULL
#define CPL 262144ULL
#define QPL 786432ULL
#define NCHUNK (4ULL*CW + 2ULL*CFF + CFC)
#define NBIAS  ((size_t)Lv*QKVS/4)
#define NTOTAL (NCHUNK + NBIAS)

__global__ __launch_bounds__(256) void conv_all_kernel(
    const float4* __restrict__ Wq, const float4* __restrict__ Wk,
    const float4* __restrict__ Wv, const float4* __restrict__ Wo,
    const float4* __restrict__ W1, const float4* __restrict__ W2,
    const float4* __restrict__ fcW,
    const float4* __restrict__ bq, const float4* __restrict__ bk,
    const float4* __restrict__ bv, float4* __restrict__ bqkv,
    __nv_bfloat162* __restrict__ qkv, __nv_bfloat162* __restrict__ wo,
    __nv_bfloat162* __restrict__ w1,  __nv_bfloat162* __restrict__ w2,
    __nv_bfloat162* __restrict__ fc)
{
    size_t i = (size_t)blockIdx.x * 256 + threadIdx.x;
    if (i >= NTOTAL) return;
    if (i >= NCHUNK) {
        size_t j = i - NCHUNK;
        int l = (int)(j / 768), r = (int)(j % 768);
        float4 s;
        if (r < 256)       s = bq[l*256 + r];
        else if (r < 512)  s = bk[l*256 + (r-256)];
        else               s = bv[l*256 + (r-512)];
        bqkv[j] = s;
        return;
    }
    float4 v;
    __nv_bfloat162* base;
    size_t dst;
    if (i < CW) {
        size_t l = i / CPL, r = i % CPL;
        v = Wq[i]; base = qkv; dst = l*QPL + r;
    } else if (i < 2*CW) {
        size_t j = i - CW, l = j / CPL, r = j % CPL;
        v = Wk[j]; base = qkv; dst = l*QPL + CPL + r;
    } else if (i < 3*CW) {
        size_t j = i - 2*CW, l = j / CPL, r = j % CPL;
        v = Wv[j]; base = qkv; dst = l*QPL + 2*CPL + r;
    } else if (i < 4*CW) {
        size_t j = i - 3*CW; v = Wo[j]; base = wo; dst = j;
    } else if (i < 4*CW + CFF) {
        size_t j = i - 4*CW; v = W1[j]; base = w1; dst = j;
    } else if (i < 4*CW + 2*CFF) {
        size_t j = i - 4*CW - CFF; v = W2[j]; base = w2; dst = j;
    } else {
        size_t j = i - 4*CW - 2*CFF; v = fcW[j]; base = fc; dst = j;
    }
    base[2*dst]   = __floats2bfloat162_rn(v.x, v.y);
    base[2*dst+1] = __floats2bfloat162_rn(v.z, v.w);
}

// ---------------- embedding (float4) + output zeroing --------------------------
__global__ void embed_kernel(const int* __restrict__ tokens,
                             const float4* __restrict__ emb,
                             const float4* __restrict__ pe,
                             float4* __restrict__ x,
                             float* __restrict__ out)
{
    int idx = blockIdx.x * blockDim.x + threadIdx.x;
    if (blockIdx.x == 0 && threadIdx.x < Bv) out[threadIdx.x] = 0.f;
    if (idx >= Mv*Dv/4) return;
    int d4 = idx & 255;
    int ms = idx >> 8;
    int s  = ms & (Sv-1);
    int t  = tokens[ms];
    float4 e = emb[(size_t)t*256 + d4];
    float4 p = pe[(size_t)s*256 + d4];
    float4 o;
    o.x = e.x*32.0f + p.x; o.y = e.y*32.0f + p.y;
    o.z = e.z*32.0f + p.z; o.w = e.w*32.0f + p.w;
    x[idx] = o;
}

// ---------------- layernorm (single global read, float4) ----------------------
__global__ __launch_bounds__(256) void ln_kernel(const float* __restrict__ x,
                                                 const float* __restrict__ g,
                                                 const float* __restrict__ b,
                                                 __nv_bfloat16* __restrict__ out)
{
    __shared__ float sred[2][8];
    int row = blockIdx.x, tid = threadIdx.x;
    float4 v = ((const float4*)(x + (size_t)row * Dv))[tid];
    float s  = v.x + v.y + v.z + v.w;
    float s2 = v.x*v.x + v.y*v.y + v.z*v.z + v.w*v.w;
    #pragma unroll
    for (int o = 16; o; o >>= 1) {
        s  += __shfl_xor_sync(0xffffffffu, s,  o);
        s2 += __shfl_xor_sync(0xffffffffu, s2, o);
    }
    int w = tid >> 5;
    if ((tid & 31) == 0) { sred[0][w] = s; sred[1][w] = s2; }
    __syncthreads();
    if (tid < 32) {
        s  = (tid < 8) ? sred[0][tid] : 0.f;
        s2 = (tid < 8) ? sred[1][tid] : 0.f;
        #pragma unroll
        for (int o = 4; o; o >>= 1) {
            s  += __shfl_xor_sync(0xffffffffu, s,  o);
            s2 += __shfl_xor_sync(0xffffffffu, s2, o);
        }
        if (tid == 0) { sred[0][0] = s; sred[1][0] = s2; }
    }
    __syncthreads();
    float mu  = sred[0][0] * (1.0f/Dv);
    float var = sred[1][0] * (1.0f/Dv) - mu*mu;
    float inv = rsqrtf(var + 1e-5f);
    float4 gg = ((const float4*)g)[tid];
    float4 bb = ((const float4*)b)[tid];
    float r0 = (v.x-mu)*inv*gg.x + bb.x;
    float r1 = (v.y-mu)*inv*gg.y + bb.y;
    float r2 = (v.z-mu)*inv*gg.z + bb.z;
    float r3 = (v.w-mu)*inv*gg.w + bb.w;
    __nv_bfloat162 p0 = __floats2bfloat162_rn(r0, r1);
    __nv_bfloat162 p1 = __floats2bfloat162_rn(r2, r3);
    uint2 pk; pk.x = *(uint32_t*)&p0; pk.y = *(uint32_t*)&p1;
    ((uint2*)(out + (size_t)row * Dv))[tid] = pk;
}

// ---------------- MMA helpers -------------------------------------------------
__device__ __forceinline__ void cp16(void* s, const void* g) {
    uint32_t sa = (uint32_t)__cvta_generic_to_shared(s);
    asm volatile("cp.async.cg.shared.global [%0], [%1], 16;\n" :: "r"(sa), "l"(g));
}
__device__ __forceinline__ void ldsm4(uint32_t* r, const void* p) {
    uint32_t a = (uint32_t)__cvta_generic_to_shared(p);
    asm volatile("ldmatrix.sync.aligned.m8n8.x4.shared.b16 {%0,%1,%2,%3}, [%4];"
        : "=r"(r[0]), "=r"(r[1]), "=r"(r[2]), "=r"(r[3]) : "r"(a));
}
__device__ __forceinline__ void ldsm4t(uint32_t* r, const void* p) {
    uint32_t a = (uint32_t)__cvta_generic_to_shared(p);
    asm volatile("ldmatrix.sync.aligned.m8n8.x4.trans.shared.b16 {%0,%1,%2,%3}, [%4];"
        : "=r"(r[0]), "=r"(r[1]), "=r"(r[2]), "=r"(r[3]) : "r"(a));
}
__device__ __forceinline__ void mma16816(float* c, const uint32_t* a, const uint32_t* b) {
    asm volatile("mma.sync.aligned.m16n8k16.row.col.f32.bf16.bf16.f32 "
        "{%0,%1,%2,%3}, {%4,%5,%6,%7}, {%8,%9}, {%0,%1,%2,%3};"
        : "+f"(c[0]), "+f"(c[1]), "+f"(c[2]), "+f"(c[3])
        : "r"(a[0]), "r"(a[1]), "r"(a[2]), "r"(a[3]), "r"(b[0]), "r"(b[1]));
}

// ---------------- bf16 tensor-core GEMM: 128x128, GBK=64, 3-stage, 2 CTA/SM ---
// warp tile 64x32; fragment double-buffer to overlap ldsm latency with MMAs
// mode 0: ->f32   1: GELU->bf16   2: +res->f32   3: ->bf16
#define GBM 128
#define GBN 128
#define GBK 64
#define PADK 72
#define STAGES 3
#define SMEM_G (STAGES * (GBM + GBN) * PADK * 2)    // 110592 B

__global__ __launch_bounds__(256, 2) void hgemm_kernel(
    const __nv_bfloat16* __restrict__ A, const __nv_bfloat16* __restrict__ Bw,
    const float* __restrict__ bias, const float* __restrict__ res,
    void* __restrict__ Cc, int Mr, int Nr, int Kr, int mode)
{
    extern __shared__ __nv_bfloat16 sm[];
    __nv_bfloat16* As = sm;
    __nv_bfloat16* Bs = sm + STAGES * GBM * PADK;

    int tid  = threadIdx.x;
    int warp = tid >> 5;
    int lane = tid & 31;
    int warp_m = warp & 1;
    int warp_n = warp >> 1;
    int row0 = blockIdx.y * GBM;
    int col0 = blockIdx.x * GBN;

    float acc[4][4][4];
    #pragma unroll
    for (int i = 0; i < 4; i++)
        #pragma unroll
        for (int j = 0; j < 4; j++)
            #pragma unroll
            for (int t = 0; t < 4; t++) acc[i][j][t] = 0.f;

    const __nv_bfloat16* Ab = A  + (size_t)row0 * Kr;
    const __nv_bfloat16* Bb = Bw + (size_t)col0 * Kr;
    int kt_total = Kr / GBK;

    auto load_stage = [&](int st, int kb) {
        __nv_bfloat16* as = As + st * GBM * PADK;
        __nv_bfloat16* bs = Bs + st * GBN * PADK;
        #pragma unroll
        for (int c = 0; c < 4; c++) {
            int idx = tid + c*256;
            int r = idx >> 3, kk = (idx & 7) * 8;
            cp16(&as[r*PADK + kk], Ab + (size_t)r*Kr + kb + kk);
            cp16(&bs[r*PADK + kk], Bb + (size_t)r*Kr + kb + kk);
        }
    };

    #pragma unroll
    for (int s = 0; s < STAGES-1; s++) {
        if (s < kt_total) load_stage(s, s*GBK);
        asm volatile("cp.async.commit_group;\n" ::: "memory");
    }

    // per-warp fragment addresses (constant across ks except k-offset)
    int a_row = warp_m*64 + (lane & 15);
    int a_koh = (lane >> 4)*8;
    int b_row = warp_n*32 + (lane & 7) + ((lane & 16) >> 1);
    int b_koh = ((lane >> 3) & 1)*8;

    for (int kt = 0; kt < kt_total; kt++) {
        asm volatile("cp.async.wait_group %0;\n" :: "n"(STAGES-2) : "memory");
        __syncthreads();

        int nk = kt + STAGES - 1;
        if (nk < kt_total) load_stage(nk % STAGES, nk*GBK);
        asm volatile("cp.async.commit_group;\n" ::: "memory");

        const __nv_bfloat16* as = As + (kt % STAGES) * GBM * PADK;
        const __nv_bfloat16* bs = Bs + (kt % STAGES) * GBN * PADK;

        uint32_t ra[2][4][4];
        uint32_t rb[2][2][4];

        // prime ks=0 fragments
        #pragma unroll
        for (int mi = 0; mi < 4; mi++)
            ldsm4(ra[0][mi], as + (a_row + mi*16)*PADK + a_koh);
        #pragma unroll
        for (int nj = 0; nj < 2; nj++)
            ldsm4(rb[0][nj], bs + (b_row + nj*16)*PADK + b_koh);

        #pragma unroll
        for (int ks = 0; ks < 4; ks++) {
            int cur = ks & 1, nxt = cur ^ 1;
            if (ks < 3) {                       // prefetch next-ks fragments
                int kof = (ks + 1) * 16;
                #pragma unroll
                for (int mi = 0; mi < 4; mi++)
                    ldsm4(ra[nxt][mi], as + (a_row + mi*16)*PADK + kof + a_koh);
                #pragma unroll
                for (int nj = 0; nj < 2; nj++)
                    ldsm4(rb[nxt][nj], bs + (b_row + nj*16)*PADK + kof + b_koh);
            }
            #pragma unroll
            for (int mi = 0; mi < 4; mi++)
                #pragma unroll
                for (int nt = 0; nt < 4; nt++)
                    mma16816(acc[mi][nt], ra[cur][mi], &rb[cur][nt >> 1][(nt & 1)*2]);
        }
    }

    #pragma unroll
    for (int mi = 0; mi < 4; mi++) {
        int rw = row0 + warp_m*64 + mi*16 + (lane >> 2);
        #pragma unroll
        for (int nt = 0; nt < 4; nt++) {
            int cw = col0 + warp_n*32 + nt*8 + (lane & 3)*2;
            float2 bb = *(const float2*)(bias + cw);
            float v0 = acc[mi][nt][0] + bb.x;
            float v1 = acc[mi][nt][1] + bb.y;
            float v2 = acc[mi][nt][2] + bb.x;
            float v3 = acc[mi][nt][3] + bb.y;
            if (mode == 0) {
                float* C = (float*)Cc;
                *(float2*)(C + (size_t)rw*Nr + cw)     = make_float2(v0, v1);
                *(float2*)(C + (size_t)(rw+8)*Nr + cw) = make_float2(v2, v3);
            } else if (mode == 1) {
                v0 = v0 * normcdff(v0); v1 = v1 * normcdff(v1);
                v2 = v2 * normcdff(v2); v3 = v3 * normcdff(v3);
                __nv_bfloat16* C = (__nv_bfloat16*)Cc;
                *(__nv_bfloat162*)(C + (size_t)rw*Nr + cw)     = __floats2bfloat162_rn(v0, v1);
                *(__nv_bfloat162*)(C + (size_t)(rw+8)*Nr + cw) = __floats2bfloat162_rn(v2, v3);
            } else if (mode == 2) {
                float* C = (float*)Cc;
                float2 r1 = *(const float2*)(res + (size_t)rw*Nr + cw);
                float2 r2 = *(const float2*)(res + (size_t)(rw+8)*Nr + cw);
                *(float2*)(C + (size_t)rw*Nr + cw)     = make_float2(v0 + r1.x, v1 + r1.y);
                *(float2*)(C + (size_t)(rw+8)*Nr + cw) = make_float2(v2 + r2.x, v3 + r2.y);
            } else {
                __nv_bfloat16* C = (__nv_bfloat16*)Cc;
                *(__nv_bfloat162*)(C + (size_t)rw*Nr + cw)     = __floats2bfloat162_rn(v0, v1);
                *(__nv_bfloat162*)(C + (size_t)(rw+8)*Nr + cw) = __floats2bfloat162_rn(v2, v3);
            }
        }
    }
}

// ---------------- MMA flash attention: 128 queries/block, 8 warps -------------
#define AQ 128
#define AK 64
#define APAD 72

__global__ __launch_bounds__(256) void attn_mma_kernel(
    const __nv_bfloat16* __restrict__ q, const __nv_bfloat16* __restrict__ k,
    const __nv_bfloat16* __restrict__ v, __nv_bfloat16* __restrict__ y)
{
    __shared__ __nv_bfloat16 Qs[AQ][APAD];
    __shared__ __nv_bfloat16 Ks[AK][APAD];
    __shared__ __nv_bfloat16 Vs[AK][APAD];

    int b = blockIdx.z, h = blockIdx.y;
    int q0 = blockIdx.x * AQ;
    int tid = threadIdx.x, wid = tid >> 5, lane = tid & 31;

    {
        int row = tid >> 1, half = (tid & 1) * 32;
        const uint4* src = (const uint4*)(q + ((size_t)(b*Sv + q0 + row))*QKVS + h*HDv + half);
        uint4* dst = (uint4*)&Qs[row][half];
        dst[0] = src[0]; dst[1] = src[1]; dst[2] = src[2]; dst[3] = src[3];
    }

    float m0 = -1e30f, m1 = -1e30f, l0 = 0.f, l1 = 0.f;
    float Oa[8][4];
    #pragma unroll
    for (int i = 0; i < 8; i++)
        #pragma unroll
        for (int j = 0; j < 4; j++) Oa[i][j] = 0.f;

    int r_lo = lane >> 2;
    int colb = (lane & 3) * 2;
    int wrow_max = q0 + wid*16 + 15;

    for (int j0 = 0; j0 <= q0 + (AQ - AK); j0 += AK) {
        __syncthreads();
        {
            int row = tid >> 2, qtr = (tid & 3) * 16;
            size_t off = ((size_t)(b*Sv + j0 + row))*QKVS + h*HDv + qtr;
            const uint4* ks = (const uint4*)(k + off);
            const uint4* vs = (const uint4*)(v + off);
            uint4* kd = (uint4*)&Ks[row][qtr];
            uint4* vd = (uint4*)&Vs[row][qtr];
            kd[0]=ks[0]; kd[1]=ks[1];
            vd[0]=vs[0]; vd[1]=vs[1];
        }
        __syncthreads();

        if (j0 > wrow_max) continue;

        float c[8][4];
        #pragma unroll
        for (int i = 0; i < 8; i++)
            #pragma unroll
            for (int j = 0; j < 4; j++) c[i][j] = 0.f;

        #pragma unroll
        for (int kk = 0; kk < 4; kk++) {
            int kof = kk * 16;
            uint32_t ra[4];
            ldsm4(ra, &Qs[wid*16 + (lane & 15)][kof + (lane >> 4)*8]);
            #pragma unroll
            for (int nt = 0; nt < 4; nt++) {
                uint32_t rb[4];
                int nn = nt*16 + (lane & 7) + ((lane & 16) >> 1);
                ldsm4(rb, &Ks[nn][kof + ((lane >> 3) & 1)*8]);
                mma16816(c[2*nt],   ra, &rb[0]);
                mma16816(c[2*nt+1], ra, &rb[2]);
            }
        }

        int row0 = q0 + wid*16 + r_lo;
        int row1 = row0 + 8;
        #pragma unroll
        for (int nt = 0; nt < 8; nt++) {
            c[nt][0] *= 0.125f; c[nt][1] *= 0.125f;
            c[nt][2] *= 0.125f; c[nt][3] *= 0.125f;
        }
        if (j0 + AK - 1 > row0) {
            #pragma unroll
            for (int nt = 0; nt < 8; nt++) {
                int col = j0 + nt*8 + colb;
                if (col   > row0) c[nt][0] = -1e30f;
                if (col+1 > row0) c[nt][1] = -1e30f;
                if (col   > row1) c[nt][2] = -1e30f;
                if (col+1 > row1) c[nt][3] = -1e30f;
            }
        }

        float rm0 = -1e30f, rm1 = -1e30f;
        #pragma unroll
        for (int nt = 0; nt < 8; nt++) {
            rm0 = fmaxf(rm0, fmaxf(c[nt][0], c[nt][1]));
            rm1 = fmaxf(rm1, fmaxf(c[nt][2], c[nt][3]));
        }
        rm0 = fmaxf(rm0, __shfl_xor_sync(0xffffffffu, rm0, 1));
        rm0 = fmaxf(rm0, __shfl_xor_sync(0xffffffffu, rm0, 2));
        rm1 = fmaxf(rm1, __shfl_xor_sync(0xffffffffu, rm1, 1));
        rm1 = fmaxf(rm1, __shfl_xor_sync(0xffffffffu, rm1, 2));

        float mn0 = fmaxf(m0, rm0), mn1 = fmaxf(m1, rm1);
        float cr0 = __expf(m0 - mn0), cr1 = __expf(m1 - mn1);
        m0 = mn0; m1 = mn1;

        float ps0 = 0.f, ps1 = 0.f;
        #pragma unroll
        for (int nt = 0; nt < 8; nt++) {
            c[nt][0] = __expf(c[nt][0] - mn0);
            c[nt][1] = __expf(c[nt][1] - mn0);
            c[nt][2] = __expf(c[nt][2] - mn1);
            c[nt][3] = __expf(c[nt][3] - mn1);
            ps0 += c[nt][0] + c[nt][1];
            ps1 += c[nt][2] + c[nt][3];
        }
        ps0 += __shfl_xor_sync(0xffffffffu, ps0, 1);
        ps0 += __shfl_xor_sync(0xffffffffu, ps0, 2);
        ps1 += __shfl_xor_sync(0xffffffffu, ps1, 1);
        ps1 += __shfl_xor_sync(0xffffffffu, ps1, 2);
        l0 = l0*cr0 + ps0;
        l1 = l1*cr1 + ps1;

        #pragma unroll
        for (int nt = 0; nt < 8; nt++) {
            Oa[nt][0] *= cr0; Oa[nt][1] *= cr0;
            Oa[nt][2] *= cr1; Oa[nt][3] *= cr1;
        }

        #pragma unroll
        for (int kt = 0; kt < 4; kt++) {
            uint32_t a[4];
            __nv_bfloat162 p0 = __floats2bfloat162_rn(c[2*kt][0],   c[2*kt][1]);
            __nv_bfloat162 p1 = __floats2bfloat162_rn(c[2*kt][2],   c[2*kt][3]);
            __nv_bfloat162 p2 = __floats2bfloat162_rn(c[2*kt+1][0], c[2*kt+1][1]);
            __nv_bfloat162 p3 = __floats2bfloat162_rn(c[2*kt+1][2], c[2*kt+1][3]);
            a[0] = *(uint32_t*)&p0; a[1] = *(uint32_t*)&p1;
            a[2] = *(uint32_t*)&p2; a[3] = *(uint32_t*)&p3;
            #pragma unroll
            for (int nt = 0; nt < 4; nt++) {
                uint32_t rv[4];
                int key = kt*16 + (lane & 7) + ((lane >> 3) & 1)*8;
                int dim = nt*16 + (lane >> 4)*8;
                ldsm4t(rv, &Vs[key][dim]);
                mma16816(Oa[2*nt],   a, &rv[0]);
                mma16816(Oa[2*nt+1], a, &rv[2]);
            }
        }
    }

    float il0 = 1.0f / l0, il1 = 1.0f / l1;
    int grow0 = q0 + wid*16 + r_lo;
    #pragma unroll
    for (int nt = 0; nt < 8; nt++) {
        int dcol = nt*8 + colb;
        __nv_bfloat16* yp0 = y + ((size_t)(b*Sv + grow0))*Dv + h*HDv + dcol;
        __nv_bfloat16* yp1 = y + ((size_t)(b*Sv + grow0 + 8))*Dv + h*HDv + dcol;
        *(__nv_bfloat162*)yp0 = __floats2bfloat162_rn(Oa[nt][0]*il0, Oa[nt][1]*il0);
        *(__nv_bfloat162*)yp1 = __floats2bfloat162_rn(Oa[nt][2]*il1, Oa[nt][3]*il1);
    }
}

// ---------------- final loss (bf16 logits, single-pass online softmax) --------
__global__ __launch_bounds__(256) void loss_kernel(const __nv_bfloat16* __restrict__ logits,
                                                   const int* __restrict__ tokens,
                                                   float* __restrict__ out)
{
    __shared__ float smax[8], ssum[8];
    int row = blockIdx.x, tid = threadIdx.x;
    const uint4* lr8 = (const uint4*)(logits + (size_t)row * Cv);

    float m = -1e30f, s = 0.f;
    #pragma unroll
    for (int c = 0; c < Cv/2048; c++) {
        uint4 u = lr8[tid + c*256];
        float2 f0 = __bfloat1622float2(*(__nv_bfloat162*)&u.x);
        float2 f1 = __bfloat1622float2(*(__nv_bfloat162*)&u.y);
        float2 f2 = __bfloat1622float2(*(__nv_bfloat162*)&u.z);
        float2 f3 = __bfloat1622float2(*(__nv_bfloat162*)&u.w);
        float vm = fmaxf(fmaxf(fmaxf(f0.x, f0.y), fmaxf(f1.x, f1.y)),
                         fmaxf(fmaxf(f2.x, f2.y), fmaxf(f3.x, f3.y)));
        if (vm > m) { s = s * __expf(m - vm); m = vm; }
        s += __expf(f0.x - m) + __expf(f0.y - m) + __expf(f1.x - m) + __expf(f1.y - m)
           + __expf(f2.x - m) + __expf(f2.y - m) + __expf(f3.x - m) + __expf(f3.y - m);
    }
    #pragma unroll
    for (int o = 16; o; o >>= 1) {
        float m2 = __shfl_xor_sync(0xffffffffu, m, o);
        float s2 = __shfl_xor_sync(0xffffffffu, s, o);
        float mn = fmaxf(m, m2);
        s = s * __expf(m - mn) + s2 * __expf(m2 - mn);
        m = mn;
    }
    int w = tid >> 5;
    if ((tid & 31) == 0) { smax[w] = m; ssum[w] = s; }
    __syncthreads();
    if (tid == 0) {
        m = smax[0]; s = ssum[0];
        #pragma unroll
        for (int i = 1; i < 8; i++) {
            float mn = fmaxf(m, smax[i]);
            s = s * __expf(m - mn) + ssum[i] * __expf(smax[i] - mn);
            m = mn;
        }
        int t = tokens[row];
        if (t != PADTOK) {
            float lt = __bfloat162float(logits[(size_t)row * Cv + t]);
            float lp = lt - m - logf(s);
            atomicAdd(&out[row / Sv], lp);
        }
    }
}

// ---------------- driver -----------------------------------------------------
static void run_hgemm(const __nv_bfloat16* A, const __nv_bfloat16* W,
                      const float* bias, const float* res,
                      void* Cc, int M_, int N_, int K_, int mode)
{
    dim3 grid(N_/GBN, M_/GBM);
    hgemm_kernel<<<grid, 256, SMEM_G>>>(A, W, bias, res, Cc, M_, N_, K_, mode);
}

extern "C" void kernel_launch(void* const* d_in, const int* in_sizes, int n_in,
                              void* d_out, int out_size)
{
    const int*   tokens = (const int*)  d_in[0];
    const float* emb    = (const float*)d_in[1];
    const float* pe     = (const float*)d_in[2];
    const float* ln1_g  = (const float*)d_in[3];
    const float* ln1_b  = (const float*)d_in[4];
    const float* Wq     = (const float*)d_in[5];
    const float* bq     = (const float*)d_in[6];
    const float* Wk     = (const float*)d_in[7];
    const float* bk     = (const float*)d_in[8];
    const float* Wv     = (const float*)d_in[9];
    const float* bv     = (const float*)d_in[10];
    const float* Wo     = (const float*)d_in[11];
    const float* bo     = (const float*)d_in[12];
    const float* ln2_g  = (const float*)d_in[13];
    const float* ln2_b  = (const float*)d_in[14];
    const float* W1     = (const float*)d_in[15];
    const float* b1     = (const float*)d_in[16];
    const float* W2     = (const float*)d_in[17];
    const float* b2     = (const float*)d_in[18];
    const float* lnf_g  = (const float*)d_in[19];
    const float* lnf_b  = (const float*)d_in[20];
    const float* fcW    = (const float*)d_in[21];
    const float* fcb    = (const float*)d_in[22];
    float* out = (float*)d_out;

    cudaFuncSetAttribute(hgemm_kernel, cudaFuncAttributeMaxDynamicSharedMemorySize, SMEM_G);

    float *x, *bqkv;
    __nv_bfloat16 *h, *y, *ff, *qkv, *logits;
    __nv_bfloat16 *wqkv, *wo_b, *w1_b, *w2_b, *fcw_b;
    cudaGetSymbolAddress((void**)&x,    g_x);
    cudaGetSymbolAddress((void**)&h,    g_h);
    cudaGetSymbolAddress((void**)&qkv,  g_qkv);
    cudaGetSymbolAddress((void**)&y,    g_y);
    cudaGetSymbolAddress((void**)&ff,   g_ff);
    cudaGetSymbolAddress((void**)&logits, g_logits);
    cudaGetSymbolAddress((void**)&wqkv, g_Wqkv);
    cudaGetSymbolAddress((void**)&bqkv, g_bqkv);
    cudaGetSymbolAddress((void**)&wo_b, g_Wo);
    cudaGetSymbolAddress((void**)&w1_b, g_W1);
    cudaGetSymbolAddress((void**)&w2_b, g_W2);
    cudaGetSymbolAddress((void**)&fcw_b, g_fcW);

    conv_all_kernel<<<(unsigned)((NTOTAL + 255)/256), 256>>>(
        (const float4*)Wq, (const float4*)Wk, (const float4*)Wv,
        (const float4*)Wo, (const float4*)W1, (const float4*)W2, (const float4*)fcW,
        (const float4*)bq, (const float4*)bk, (const float4*)bv, (float4*)bqkv,
        (__nv_bfloat162*)wqkv, (__nv_bfloat162*)wo_b,
        (__nv_bfloat162*)w1_b, (__nv_bfloat162*)w2_b, (__nv_bfloat162*)fcw_b);
    embed_kernel<<<(Mv*Dv/4 + 255)/256, 256>>>(tokens, (const float4*)emb,
                                               (const float4*)pe, (float4*)x, out);

    for (int i = 0; i < Lv; i++) {
        const __nv_bfloat16* wl  = wqkv + (size_t)i*QKVS*Dv;
        const float*         bl  = bqkv + (size_t)i*QKVS;
        const __nv_bfloat16* wo  = wo_b + (size_t)i*Dv*Dv;
        const __nv_bfloat16* w1  = w1_b + (size_t)i*FFv*Dv;
        const __nv_bfloat16* w2  = w2_b + (size_t)i*Dv*FFv;

        ln_kernel<<<Mv, 256>>>(x, ln1_g + i*Dv, ln1_b + i*Dv, h);
        run_hgemm(h, wl, bl, nullptr, qkv, Mv, QKVS, Dv, 3);

        dim3 agrid(Sv/AQ, Hv, Bv);
        attn_mma_kernel<<<agrid, 256>>>(qkv, qkv + Dv, qkv + 2*Dv, y);

        run_hgemm(y, wo, bo + i*Dv, x, x, Mv, Dv, Dv, 2);

        ln_kernel<<<Mv, 256>>>(x, ln2_g + i*Dv, ln2_b + i*Dv, h);
        run_hgemm(h, w1, b1 + i*FFv, nullptr, ff, Mv, FFv, Dv, 1);
        run_hgemm(ff, w2, b2 + i*Dv, x, x, Mv, Dv, FFv, 2);
    }

    ln_kernel<<<Mv, 256>>>(x, lnf_g, lnf_b, h);
    run_hgemm(h, fcw_b, fcb, nullptr, logits, Mv, Cv, Dv, 3);

    loss_kernel<<<Mv, 256>>>(logits, tokens, out);
}

// round 15
// speedup vs baseline: 1.0268x; 1.0268x over previous
#include <cuda_runtime.h>
#include <cuda_bf16.h>
#include <math.h>
#include <stdint.h>

#define Bv 4
#define Sv 1024
#define Dv 1024
#define Hv 16
#define Lv 12
#define Cv 8192
#define FFv 4096
#define HDv 64
#define Mv (Bv*Sv)
#define PADTOK 2
#define QKVS (3*Dv)

// ---------------- scratch ----------------------------------------------------
__device__ float g_x[Mv*Dv];
__device__ __nv_bfloat16 g_h[Mv*Dv];
__device__ __nv_bfloat16 g_qkv[(size_t)Mv*QKVS];
__device__ __nv_bfloat16 g_y[Mv*Dv];
__device__ __nv_bfloat16 g_ff[(size_t)Mv*FFv];
__device__ __nv_bfloat16 g_logits[(size_t)Mv*Cv];

__device__ __nv_bfloat16 g_Wqkv[(size_t)Lv*QKVS*Dv];
__device__ float         g_bqkv[(size_t)Lv*QKVS];
__device__ __nv_bfloat16 g_Wo[(size_t)Lv*Dv*Dv];
__device__ __nv_bfloat16 g_W1[(size_t)Lv*FFv*Dv];
__device__ __nv_bfloat16 g_W2[(size_t)Lv*Dv*FFv];
__device__ __nv_bfloat16 g_fcW[(size_t)Cv*Dv];

// ---------------- fused weight conversion + bias packing ----------------------
#define CW  3145728ULL
#define CFF 12582912ULL
#define CFC 2097152ULL
#define CPL 262144ULL
#define QPL 786432ULL
#define NCHUNK (4ULL*CW + 2ULL*CFF + CFC)
#define NBIAS  ((size_t)Lv*QKVS/4)
#define NTOTAL (NCHUNK + NBIAS)

__global__ __launch_bounds__(256) void conv_all_kernel(
    const float4* __restrict__ Wq, const float4* __restrict__ Wk,
    const float4* __restrict__ Wv, const float4* __restrict__ Wo,
    const float4* __restrict__ W1, const float4* __restrict__ W2,
    const float4* __restrict__ fcW,
    const float4* __restrict__ bq, const float4* __restrict__ bk,
    const float4* __restrict__ bv, float4* __restrict__ bqkv,
    __nv_bfloat162* __restrict__ qkv, __nv_bfloat162* __restrict__ wo,
    __nv_bfloat162* __restrict__ w1,  __nv_bfloat162* __restrict__ w2,
    __nv_bfloat162* __restrict__ fc)
{
    size_t i = (size_t)blockIdx.x * 256 + threadIdx.x;
    if (i >= NTOTAL) return;
    if (i >= NCHUNK) {
        size_t j = i - NCHUNK;
        int l = (int)(j / 768), r = (int)(j % 768);
        float4 s;
        if (r < 256)       s = bq[l*256 + r];
        else if (r < 512)  s = bk[l*256 + (r-256)];
        else               s = bv[l*256 + (r-512)];
        bqkv[j] = s;
        return;
    }
    float4 v;
    __nv_bfloat162* base;
    size_t dst;
    if (i < CW) {
        size_t l = i / CPL, r = i % CPL;
        v = Wq[i]; base = qkv; dst = l*QPL + r;
    } else if (i < 2*CW) {
        size_t j = i - CW, l = j / CPL, r = j % CPL;
        v = Wk[j]; base = qkv; dst = l*QPL + CPL + r;
    } else if (i < 3*CW) {
        size_t j = i - 2*CW, l = j / CPL, r = j % CPL;
        v = Wv[j]; base = qkv; dst = l*QPL + 2*CPL + r;
    } else if (i < 4*CW) {
        size_t j = i - 3*CW; v = Wo[j]; base = wo; dst = j;
    } else if (i < 4*CW + CFF) {
        size_t j = i - 4*CW; v = W1[j]; base = w1; dst = j;
    } else if (i < 4*CW + 2*CFF) {
        size_t j = i - 4*CW - CFF; v = W2[j]; base = w2; dst = j;
    } else {
        size_t j = i - 4*CW - 2*CFF; v = fcW[j]; base = fc; dst = j;
    }
    base[2*dst]   = __floats2bfloat162_rn(v.x, v.y);
    base[2*dst+1] = __floats2bfloat162_rn(v.z, v.w);
}

// ---------------- embedding (float4) + output zeroing --------------------------
__global__ void embed_kernel(const int* __restrict__ tokens,
                             const float4* __restrict__ emb,
                             const float4* __restrict__ pe,
                             float4* __restrict__ x,
                             float* __restrict__ out)
{
    int idx = blockIdx.x * blockDim.x + threadIdx.x;
    if (blockIdx.x == 0 && threadIdx.x < Bv) out[threadIdx.x] = 0.f;
    if (idx >= Mv*Dv/4) return;
    int d4 = idx & 255;
    int ms = idx >> 8;
    int s  = ms & (Sv-1);
    int t  = tokens[ms];
    float4 e = emb[(size_t)t*256 + d4];
    float4 p = pe[(size_t)s*256 + d4];
    float4 o;
    o.x = e.x*32.0f + p.x; o.y = e.y*32.0f + p.y;
    o.z = e.z*32.0f + p.z; o.w = e.w*32.0f + p.w;
    x[idx] = o;
}

// ---------------- layernorm (single global read, float4) ----------------------
__global__ __launch_bounds__(256) void ln_kernel(const float* __restrict__ x,
                                                 const float* __restrict__ g,
                                                 const float* __restrict__ b,
                                                 __nv_bfloat16* __restrict__ out)
{
    __shared__ float sred[2][8];
    int row = blockIdx.x, tid = threadIdx.x;
    float4 v = ((const float4*)(x + (size_t)row * Dv))[tid];
    float s  = v.x + v.y + v.z + v.w;
    float s2 = v.x*v.x + v.y*v.y + v.z*v.z + v.w*v.w;
    #pragma unroll
    for (int o = 16; o; o >>= 1) {
        s  += __shfl_xor_sync(0xffffffffu, s,  o);
        s2 += __shfl_xor_sync(0xffffffffu, s2, o);
    }
    int w = tid >> 5;
    if ((tid & 31) == 0) { sred[0][w] = s; sred[1][w] = s2; }
    __syncthreads();
    if (tid < 32) {
        s  = (tid < 8) ? sred[0][tid] : 0.f;
        s2 = (tid < 8) ? sred[1][tid] : 0.f;
        #pragma unroll
        for (int o = 4; o; o >>= 1) {
            s  += __shfl_xor_sync(0xffffffffu, s,  o);
            s2 += __shfl_xor_sync(0xffffffffu, s2, o);
        }
        if (tid == 0) { sred[0][0] = s; sred[1][0] = s2; }
    }
    __syncthreads();
    float mu  = sred[0][0] * (1.0f/Dv);
    float var = sred[1][0] * (1.0f/Dv) - mu*mu;
    float inv = rsqrtf(var + 1e-5f);
    float4 gg = ((const float4*)g)[tid];
    float4 bb = ((const float4*)b)[tid];
    float r0 = (v.x-mu)*inv*gg.x + bb.x;
    float r1 = (v.y-mu)*inv*gg.y + bb.y;
    float r2 = (v.z-mu)*inv*gg.z + bb.z;
    float r3 = (v.w-mu)*inv*gg.w + bb.w;
    __nv_bfloat162 p0 = __floats2bfloat162_rn(r0, r1);
    __nv_bfloat162 p1 = __floats2bfloat162_rn(r2, r3);
    uint2 pk; pk.x = *(uint32_t*)&p0; pk.y = *(uint32_t*)&p1;
    ((uint2*)(out + (size_t)row * Dv))[tid] = pk;
}

// ---------------- MMA helpers -------------------------------------------------
__device__ __forceinline__ void cp16(void* s, const void* g) {
    uint32_t sa = (uint32_t)__cvta_generic_to_shared(s);
    asm volatile("cp.async.cg.shared.global [%0], [%1], 16;\n" :: "r"(sa), "l"(g));
}
__device__ __forceinline__ void ldsm4(uint32_t* r, const void* p) {
    uint32_t a = (uint32_t)__cvta_generic_to_shared(p);
    asm volatile("ldmatrix.sync.aligned.m8n8.x4.shared.b16 {%0,%1,%2,%3}, [%4];"
        : "=r"(r[0]), "=r"(r[1]), "=r"(r[2]), "=r"(r[3]) : "r"(a));
}
__device__ __forceinline__ void ldsm4t(uint32_t* r, const void* p) {
    uint32_t a = (uint32_t)__cvta_generic_to_shared(p);
    asm volatile("ldmatrix.sync.aligned.m8n8.x4.trans.shared.b16 {%0,%1,%2,%3}, [%4];"
        : "=r"(r[0]), "=r"(r[1]), "=r"(r[2]), "=r"(r[3]) : "r"(a));
}
__device__ __forceinline__ void mma16816(float* c, const uint32_t* a, const uint32_t* b) {
    asm volatile("mma.sync.aligned.m16n8k16.row.col.f32.bf16.bf16.f32 "
        "{%0,%1,%2,%3}, {%4,%5,%6,%7}, {%8,%9}, {%0,%1,%2,%3};"
        : "+f"(c[0]), "+f"(c[1]), "+f"(c[2]), "+f"(c[3])
        : "r"(a[0]), "r"(a[1]), "r"(a[2]), "r"(a[3]), "r"(b[0]), "r"(b[1]));
}

// ---------------- bf16 tensor-core GEMM: 128x128, GBK=64, 3-stage, 2 CTA/SM ---
// warp tile 64x32 (8 warps), 4 K=16 sub-steps per stage (round-13 proven config)
// mode 0: ->f32   1: GELU->bf16   2: +res->f32   3: ->bf16
#define GBM 128
#define GBN 128
#define GBK 64
#define PADK 72
#define STAGES 3
#define SMEM_G (STAGES * (GBM + GBN) * PADK * 2)    // 110592 B

__global__ __launch_bounds__(256, 2) void hgemm_kernel(
    const __nv_bfloat16* __restrict__ A, const __nv_bfloat16* __restrict__ Bw,
    const float* __restrict__ bias, const float* __restrict__ res,
    void* __restrict__ Cc, int Mr, int Nr, int Kr, int mode)
{
    extern __shared__ __nv_bfloat16 sm[];
    __nv_bfloat16* As = sm;
    __nv_bfloat16* Bs = sm + STAGES * GBM * PADK;

    int tid  = threadIdx.x;
    int warp = tid >> 5;
    int lane = tid & 31;
    int warp_m = warp & 1;
    int warp_n = warp >> 1;
    int row0 = blockIdx.y * GBM;
    int col0 = blockIdx.x * GBN;

    float acc[4][4][4];
    #pragma unroll
    for (int i = 0; i < 4; i++)
        #pragma unroll
        for (int j = 0; j < 4; j++)
            #pragma unroll
            for (int t = 0; t < 4; t++) acc[i][j][t] = 0.f;

    const __nv_bfloat16* Ab = A  + (size_t)row0 * Kr;
    const __nv_bfloat16* Bb = Bw + (size_t)col0 * Kr;
    int kt_total = Kr / GBK;

    auto load_stage = [&](int st, int kb) {
        __nv_bfloat16* as = As + st * GBM * PADK;
        __nv_bfloat16* bs = Bs + st * GBN * PADK;
        #pragma unroll
        for (int c = 0; c < 4; c++) {
            int idx = tid + c*256;
            int r = idx >> 3, kk = (idx & 7) * 8;
            cp16(&as[r*PADK + kk], Ab + (size_t)r*Kr + kb + kk);
            cp16(&bs[r*PADK + kk], Bb + (size_t)r*Kr + kb + kk);
        }
    };

    #pragma unroll
    for (int s = 0; s < STAGES-1; s++) {
        if (s < kt_total) load_stage(s, s*GBK);
        asm volatile("cp.async.commit_group;\n" ::: "memory");
    }

    for (int kt = 0; kt < kt_total; kt++) {
        asm volatile("cp.async.wait_group %0;\n" :: "n"(STAGES-2) : "memory");
        __syncthreads();

        int nk = kt + STAGES - 1;
        if (nk < kt_total) load_stage(nk % STAGES, nk*GBK);
        asm volatile("cp.async.commit_group;\n" ::: "memory");

        const __nv_bfloat16* as = As + (kt % STAGES) * GBM * PADK;
        const __nv_bfloat16* bs = Bs + (kt % STAGES) * GBN * PADK;

        #pragma unroll
        for (int ks = 0; ks < 4; ks++) {
            int kof = ks * 16;
            uint32_t ra[4][4];
            #pragma unroll
            for (int mi = 0; mi < 4; mi++) {
                int rr = warp_m*64 + mi*16 + (lane & 15);
                ldsm4(ra[mi], as + rr*PADK + kof + (lane >> 4)*8);
            }
            uint32_t rb[2][4];
            #pragma unroll
            for (int nj = 0; nj < 2; nj++) {
                int nn = warp_n*32 + nj*16 + (lane & 7) + ((lane & 16) >> 1);
                ldsm4(rb[nj], bs + nn*PADK + kof + ((lane >> 3) & 1)*8);
            }
            #pragma unroll
            for (int mi = 0; mi < 4; mi++)
                #pragma unroll
                for (int nt = 0; nt < 4; nt++)
                    mma16816(acc[mi][nt], ra[mi], &rb[nt >> 1][(nt & 1)*2]);
        }
    }

    #pragma unroll
    for (int mi = 0; mi < 4; mi++) {
        int rw = row0 + warp_m*64 + mi*16 + (lane >> 2);
        #pragma unroll
        for (int nt = 0; nt < 4; nt++) {
            int cw = col0 + warp_n*32 + nt*8 + (lane & 3)*2;
            float2 bb = *(const float2*)(bias + cw);
            float v0 = acc[mi][nt][0] + bb.x;
            float v1 = acc[mi][nt][1] + bb.y;
            float v2 = acc[mi][nt][2] + bb.x;
            float v3 = acc[mi][nt][3] + bb.y;
            if (mode == 0) {
                float* C = (float*)Cc;
                *(float2*)(C + (size_t)rw*Nr + cw)     = make_float2(v0, v1);
                *(float2*)(C + (size_t)(rw+8)*Nr + cw) = make_float2(v2, v3);
            } else if (mode == 1) {
                v0 = v0 * normcdff(v0); v1 = v1 * normcdff(v1);
                v2 = v2 * normcdff(v2); v3 = v3 * normcdff(v3);
                __nv_bfloat16* C = (__nv_bfloat16*)Cc;
                *(__nv_bfloat162*)(C + (size_t)rw*Nr + cw)     = __floats2bfloat162_rn(v0, v1);
                *(__nv_bfloat162*)(C + (size_t)(rw+8)*Nr + cw) = __floats2bfloat162_rn(v2, v3);
            } else if (mode == 2) {
                float* C = (float*)Cc;
                float2 r1 = *(const float2*)(res + (size_t)rw*Nr + cw);
                float2 r2 = *(const float2*)(res + (size_t)(rw+8)*Nr + cw);
                *(float2*)(C + (size_t)rw*Nr + cw)     = make_float2(v0 + r1.x, v1 + r1.y);
                *(float2*)(C + (size_t)(rw+8)*Nr + cw) = make_float2(v2 + r2.x, v3 + r2.y);
            } else {
                __nv_bfloat16* C = (__nv_bfloat16*)Cc;
                *(__nv_bfloat162*)(C + (size_t)rw*Nr + cw)     = __floats2bfloat162_rn(v0, v1);
                *(__nv_bfloat162*)(C + (size_t)(rw+8)*Nr + cw) = __floats2bfloat162_rn(v2, v3);
            }
        }
    }
}

// ---------------- MMA flash attention: 128 queries/block, 8 warps -------------
#define AQ 128
#define AK 64
#define APAD 72

__global__ __launch_bounds__(256) void attn_mma_kernel(
    const __nv_bfloat16* __restrict__ q, const __nv_bfloat16* __restrict__ k,
    const __nv_bfloat16* __restrict__ v, __nv_bfloat16* __restrict__ y)
{
    __shared__ __nv_bfloat16 Qs[AQ][APAD];
    __shared__ __nv_bfloat16 Ks[AK][APAD];
    __shared__ __nv_bfloat16 Vs[AK][APAD];

    int b = blockIdx.z, h = blockIdx.y;
    int q0 = blockIdx.x * AQ;
    int tid = threadIdx.x, wid = tid >> 5, lane = tid & 31;

    {
        int row = tid >> 1, half = (tid & 1) * 32;
        const uint4* src = (const uint4*)(q + ((size_t)(b*Sv + q0 + row))*QKVS + h*HDv + half);
        uint4* dst = (uint4*)&Qs[row][half];
        dst[0] = src[0]; dst[1] = src[1]; dst[2] = src[2]; dst[3] = src[3];
    }

    float m0 = -1e30f, m1 = -1e30f, l0 = 0.f, l1 = 0.f;
    float Oa[8][4];
    #pragma unroll
    for (int i = 0; i < 8; i++)
        #pragma unroll
        for (int j = 0; j < 4; j++) Oa[i][j] = 0.f;

    int r_lo = lane >> 2;
    int colb = (lane & 3) * 2;
    int wrow_max = q0 + wid*16 + 15;

    for (int j0 = 0; j0 <= q0 + (AQ - AK); j0 += AK) {
        __syncthreads();
        {
            int row = tid >> 2, qtr = (tid & 3) * 16;
            size_t off = ((size_t)(b*Sv + j0 + row))*QKVS + h*HDv + qtr;
            const uint4* ks = (const uint4*)(k + off);
            const uint4* vs = (const uint4*)(v + off);
            uint4* kd = (uint4*)&Ks[row][qtr];
            uint4* vd = (uint4*)&Vs[row][qtr];
            kd[0]=ks[0]; kd[1]=ks[1];
            vd[0]=vs[0]; vd[1]=vs[1];
        }
        __syncthreads();

        if (j0 > wrow_max) continue;

        float c[8][4];
        #pragma unroll
        for (int i = 0; i < 8; i++)
            #pragma unroll
            for (int j = 0; j < 4; j++) c[i][j] = 0.f;

        #pragma unroll
        for (int kk = 0; kk < 4; kk++) {
            int kof = kk * 16;
            uint32_t ra[4];
            ldsm4(ra, &Qs[wid*16 + (lane & 15)][kof + (lane >> 4)*8]);
            #pragma unroll
            for (int nt = 0; nt < 4; nt++) {
                uint32_t rb[4];
                int nn = nt*16 + (lane & 7) + ((lane & 16) >> 1);
                ldsm4(rb, &Ks[nn][kof + ((lane >> 3) & 1)*8]);
                mma16816(c[2*nt],   ra, &rb[0]);
                mma16816(c[2*nt+1], ra, &rb[2]);
            }
        }

        int row0 = q0 + wid*16 + r_lo;
        int row1 = row0 + 8;
        #pragma unroll
        for (int nt = 0; nt < 8; nt++) {
            c[nt][0] *= 0.125f; c[nt][1] *= 0.125f;
            c[nt][2] *= 0.125f; c[nt][3] *= 0.125f;
        }
        if (j0 + AK - 1 > row0) {
            #pragma unroll
            for (int nt = 0; nt < 8; nt++) {
                int col = j0 + nt*8 + colb;
                if (col   > row0) c[nt][0] = -1e30f;
                if (col+1 > row0) c[nt][1] = -1e30f;
                if (col   > row1) c[nt][2] = -1e30f;
                if (col+1 > row1) c[nt][3] = -1e30f;
            }
        }

        float rm0 = -1e30f, rm1 = -1e30f;
        #pragma unroll
        for (int nt = 0; nt < 8; nt++) {
            rm0 = fmaxf(rm0, fmaxf(c[nt][0], c[nt][1]));
            rm1 = fmaxf(rm1, fmaxf(c[nt][2], c[nt][3]));
        }
        rm0 = fmaxf(rm0, __shfl_xor_sync(0xffffffffu, rm0, 1));
        rm0 = fmaxf(rm0, __shfl_xor_sync(0xffffffffu, rm0, 2));
        rm1 = fmaxf(rm1, __shfl_xor_sync(0xffffffffu, rm1, 1));
        rm1 = fmaxf(rm1, __shfl_xor_sync(0xffffffffu, rm1, 2));

        float mn0 = fmaxf(m0, rm0), mn1 = fmaxf(m1, rm1);
        float cr0 = __expf(m0 - mn0), cr1 = __expf(m1 - mn1);
        m0 = mn0; m1 = mn1;

        float ps0 = 0.f, ps1 = 0.f;
        #pragma unroll
        for (int nt = 0; nt < 8; nt++) {
            c[nt][0] = __expf(c[nt][0] - mn0);
            c[nt][1] = __expf(c[nt][1] - mn0);
            c[nt][2] = __expf(c[nt][2] - mn1);
            c[nt][3] = __expf(c[nt][3] - mn1);
            ps0 += c[nt][0] + c[nt][1];
            ps1 += c[nt][2] + c[nt][3];
        }
        ps0 += __shfl_xor_sync(0xffffffffu, ps0, 1);
        ps0 += __shfl_xor_sync(0xffffffffu, ps0, 2);
        ps1 += __shfl_xor_sync(0xffffffffu, ps1, 1);
        ps1 += __shfl_xor_sync(0xffffffffu, ps1, 2);
        l0 = l0*cr0 + ps0;
        l1 = l1*cr1 + ps1;

        #pragma unroll
        for (int nt = 0; nt < 8; nt++) {
            Oa[nt][0] *= cr0; Oa[nt][1] *= cr0;
            Oa[nt][2] *= cr1; Oa[nt][3] *= cr1;
        }

        #pragma unroll
        for (int kt = 0; kt < 4; kt++) {
            uint32_t a[4];
            __nv_bfloat162 p0 = __floats2bfloat162_rn(c[2*kt][0],   c[2*kt][1]);
            __nv_bfloat162 p1 = __floats2bfloat162_rn(c[2*kt][2],   c[2*kt][3]);
            __nv_bfloat162 p2 = __floats2bfloat162_rn(c[2*kt+1][0], c[2*kt+1][1]);
            __nv_bfloat162 p3 = __floats2bfloat162_rn(c[2*kt+1][2], c[2*kt+1][3]);
            a[0] = *(uint32_t*)&p0; a[1] = *(uint32_t*)&p1;
            a[2] = *(uint32_t*)&p2; a[3] = *(uint32_t*)&p3;
            #pragma unroll
            for (int nt = 0; nt < 4; nt++) {
                uint32_t rv[4];
                int key = kt*16 + (lane & 7) + ((lane >> 3) & 1)*8;
                int dim = nt*16 + (lane >> 4)*8;
                ldsm4t(rv, &Vs[key][dim]);
                mma16816(Oa[2*nt],   a, &rv[0]);
                mma16816(Oa[2*nt+1], a, &rv[2]);
            }
        }
    }

    float il0 = 1.0f / l0, il1 = 1.0f / l1;
    int grow0 = q0 + wid*16 + r_lo;
    #pragma unroll
    for (int nt = 0; nt < 8; nt++) {
        int dcol = nt*8 + colb;
        __nv_bfloat16* yp0 = y + ((size_t)(b*Sv + grow0))*Dv + h*HDv + dcol;
        __nv_bfloat16* yp1 = y + ((size_t)(b*Sv + grow0 + 8))*Dv + h*HDv + dcol;
        *(__nv_bfloat162*)yp0 = __floats2bfloat162_rn(Oa[nt][0]*il0, Oa[nt][1]*il0);
        *(__nv_bfloat162*)yp1 = __floats2bfloat162_rn(Oa[nt][2]*il1, Oa[nt][3]*il1);
    }
}

// ---------------- final loss (bf16 logits, single-pass online softmax) --------
__global__ __launch_bounds__(256) void loss_kernel(const __nv_bfloat16* __restrict__ logits,
                                                   const int* __restrict__ tokens,
                                                   float* __restrict__ out)
{
    __shared__ float smax[8], ssum[8];
    int row = blockIdx.x, tid = threadIdx.x;
    const uint4* lr8 = (const uint4*)(logits + (size_t)row * Cv);

    float m = -1e30f, s = 0.f;
    #pragma unroll
    for (int c = 0; c < Cv/2048; c++) {
        uint4 u = lr8[tid + c*256];
        float2 f0 = __bfloat1622float2(*(__nv_bfloat162*)&u.x);
        float2 f1 = __bfloat1622float2(*(__nv_bfloat162*)&u.y);
        float2 f2 = __bfloat1622float2(*(__nv_bfloat162*)&u.z);
        float2 f3 = __bfloat1622float2(*(__nv_bfloat162*)&u.w);
        float vm = fmaxf(fmaxf(fmaxf(f0.x, f0.y), fmaxf(f1.x, f1.y)),
                         fmaxf(fmaxf(f2.x, f2.y), fmaxf(f3.x, f3.y)));
        if (vm > m) { s = s * __expf(m - vm); m = vm; }
        s += __expf(f0.x - m) + __expf(f0.y - m) + __expf(f1.x - m) + __expf(f1.y - m)
           + __expf(f2.x - m) + __expf(f2.y - m) + __expf(f3.x - m) + __expf(f3.y - m);
    }
    #pragma unroll
    for (int o = 16; o; o >>= 1) {
        float m2 = __shfl_xor_sync(0xffffffffu, m, o);
        float s2 = __shfl_xor_sync(0xffffffffu, s, o);
        float mn = fmaxf(m, m2);
        s = s * __expf(m - mn) + s2 * __expf(m2 - mn);
        m = mn;
    }
    int w = tid >> 5;
    if ((tid & 31) == 0) { smax[w] = m; ssum[w] = s; }
    __syncthreads();
    if (tid == 0) {
        m = smax[0]; s = ssum[0];
        #pragma unroll
        for (int i = 1; i < 8; i++) {
            float mn = fmaxf(m, smax[i]);
            s = s * __expf(m - mn) + ssum[i] * __expf(smax[i] - mn);
            m = mn;
        }
        int t = tokens[row];
        if (t != PADTOK) {
            float lt = __bfloat162float(logits[(size_t)row * Cv + t]);
            float lp = lt - m - logf(s);
            atomicAdd(&out[row / Sv], lp);
        }
    }
}

// ---------------- driver -----------------------------------------------------
static void run_hgemm(const __nv_bfloat16* A, const __nv_bfloat16* W,
                      const float* bias, const float* res,
                      void* Cc, int M_, int N_, int K_, int mode)
{
    dim3 grid(N_/GBN, M_/GBM);
    hgemm_kernel<<<grid, 256, SMEM_G>>>(A, W, bias, res, Cc, M_, N_, K_, mode);
}

extern "C" void kernel_launch(void* const* d_in, const int* in_sizes, int n_in,
                              void* d_out, int out_size)
{
    const int*   tokens = (const int*)  d_in[0];
    const float* emb    = (const float*)d_in[1];
    const float* pe     = (const float*)d_in[2];
    const float* ln1_g  = (const float*)d_in[3];
    const float* ln1_b  = (const float*)d_in[4];
    const float* Wq     = (const float*)d_in[5];
    const float* bq     = (const float*)d_in[6];
    const float* Wk     = (const float*)d_in[7];
    const float* bk     = (const float*)d_in[8];
    const float* Wv     = (const float*)d_in[9];
    const float* bv     = (const float*)d_in[10];
    const float* Wo     = (const float*)d_in[11];
    const float* bo     = (const float*)d_in[12];
    const float* ln2_g  = (const float*)d_in[13];
    const float* ln2_b  = (const float*)d_in[14];
    const float* W1     = (const float*)d_in[15];
    const float* b1     = (const float*)d_in[16];
    const float* W2     = (const float*)d_in[17];
    const float* b2     = (const float*)d_in[18];
    const float* lnf_g  = (const float*)d_in[19];
    const float* lnf_b  = (const float*)d_in[20];
    const float* fcW    = (const float*)d_in[21];
    const float* fcb    = (const float*)d_in[22];
    float* out = (float*)d_out;

    cudaFuncSetAttribute(hgemm_kernel, cudaFuncAttributeMaxDynamicSharedMemorySize, SMEM_G);

    float *x, *bqkv;
    __nv_bfloat16 *h, *y, *ff, *qkv, *logits;
    __nv_bfloat16 *wqkv, *wo_b, *w1_b, *w2_b, *fcw_b;
    cudaGetSymbolAddress((void**)&x,    g_x);
    cudaGetSymbolAddress((void**)&h,    g_h);
    cudaGetSymbolAddress((void**)&qkv,  g_qkv);
    cudaGetSymbolAddress((void**)&y,    g_y);
    cudaGetSymbolAddress((void**)&ff,   g_ff);
    cudaGetSymbolAddress((void**)&logits, g_logits);
    cudaGetSymbolAddress((void**)&wqkv, g_Wqkv);
    cudaGetSymbolAddress((void**)&bqkv, g_bqkv);
    cudaGetSymbolAddress((void**)&wo_b, g_Wo);
    cudaGetSymbolAddress((void**)&w1_b, g_W1);
    cudaGetSymbolAddress((void**)&w2_b, g_W2);
    cudaGetSymbolAddress((void**)&fcw_b, g_fcW);

    conv_all_kernel<<<(unsigned)((NTOTAL + 255)/256), 256>>>(
        (const float4*)Wq, (const float4*)Wk, (const float4*)Wv,
        (const float4*)Wo, (const float4*)W1, (const float4*)W2, (const float4*)fcW,
        (const float4*)bq, (const float4*)bk, (const float4*)bv, (float4*)bqkv,
        (__nv_bfloat162*)wqkv, (__nv_bfloat162*)wo_b,
        (__nv_bfloat162*)w1_b, (__nv_bfloat162*)w2_b, (__nv_bfloat162*)fcw_b);
    embed_kernel<<<(Mv*Dv/4 + 255)/256, 256>>>(tokens, (const float4*)emb,
                                               (const float4*)pe, (float4*)x, out);

    for (int i = 0; i < Lv; i++) {
        const __nv_bfloat16* wl  = wqkv + (size_t)i*QKVS*Dv;
        const float*         bl  = bqkv + (size_t)i*QKVS;
        const __nv_bfloat16* wo  = wo_b + (size_t)i*Dv*Dv;
        const __nv_bfloat16* w1  = w1_b + (size_t)i*FFv*Dv;
        const __nv_bfloat16* w2  = w2_b + (size_t)i*Dv*FFv;

        ln_kernel<<<Mv, 256>>>(x, ln1_g + i*Dv, ln1_b + i*Dv, h);
        run_hgemm(h, wl, bl, nullptr, qkv, Mv, QKVS, Dv, 3);

        dim3 agrid(Sv/AQ, Hv, Bv);
        attn_mma_kernel<<<agrid, 256>>>(qkv, qkv + Dv, qkv + 2*Dv, y);

        run_hgemm(y, wo, bo + i*Dv, x, x, Mv, Dv, Dv, 2);

        ln_kernel<<<Mv, 256>>>(x, ln2_g + i*Dv, ln2_b + i*Dv, h);
        run_hgemm(h, w1, b1 + i*FFv, nullptr, ff, Mv, FFv, Dv, 1);
        run_hgemm(ff, w2, b2 + i*Dv, x, x, Mv, Dv, FFv, 2);
    }

    ln_kernel<<<Mv, 256>>>(x, lnf_g, lnf_b, h);
    run_hgemm(h, fcw_b, fcb, nullptr, logits, Mv, Cv, Dv, 3);

    loss_kernel<<<Mv, 256>>>(logits, tokens, out);
}

// round 16
// speedup vs baseline: 1.0459x; 1.0185x over previous
#include <cuda_runtime.h>
#include <cuda_bf16.h>
#include <math.h>
#include <stdint.h>

#define Bv 4
#define Sv 1024
#define Dv 1024
#define Hv 16
#define Lv 12
#define Cv 8192
#define FFv 4096
#define HDv 64
#define Mv (Bv*Sv)
#define PADTOK 2
#define QKVS (3*Dv)

// ---------------- scratch ----------------------------------------------------
__device__ float g_x[Mv*Dv];
__device__ __nv_bfloat16 g_h[Mv*Dv];
__device__ __nv_bfloat16 g_qkv[(size_t)Mv*QKVS];
__device__ __nv_bfloat16 g_y[Mv*Dv];
__device__ __nv_bfloat16 g_ff[(size_t)Mv*FFv];
__device__ __nv_bfloat16 g_logits[(size_t)Mv*Cv];

__device__ __nv_bfloat16 g_Wqkv[(size_t)Lv*QKVS*Dv];
__device__ float         g_bqkv[(size_t)Lv*QKVS];
__device__ __nv_bfloat16 g_Wo[(size_t)Lv*Dv*Dv];
__device__ __nv_bfloat16 g_W1[(size_t)Lv*FFv*Dv];
__device__ __nv_bfloat16 g_W2[(size_t)Lv*Dv*FFv];
__device__ __nv_bfloat16 g_fcW[(size_t)Cv*Dv];

// ---------------- fused weight conversion + bias packing ----------------------
#define CW  3145728ULL
#define CFF 12582912ULL
#define CFC 2097152ULL
#define CPL 262144ULL
#define QPL 786432ULL
#define NCHUNK (4ULL*CW + 2ULL*CFF + CFC)
#define NBIAS  ((size_t)Lv*QKVS/4)
#define NTOTAL (NCHUNK + NBIAS)

__global__ __launch_bounds__(256) void conv_all_kernel(
    const float4* __restrict__ Wq, const float4* __restrict__ Wk,
    const float4* __restrict__ Wv, const float4* __restrict__ Wo,
    const float4* __restrict__ W1, const float4* __restrict__ W2,
    const float4* __restrict__ fcW,
    const float4* __restrict__ bq, const float4* __restrict__ bk,
    const float4* __restrict__ bv, float4* __restrict__ bqkv,
    __nv_bfloat162* __restrict__ qkv, __nv_bfloat162* __restrict__ wo,
    __nv_bfloat162* __restrict__ w1,  __nv_bfloat162* __restrict__ w2,
    __nv_bfloat162* __restrict__ fc)
{
    size_t i = (size_t)blockIdx.x * 256 + threadIdx.x;
    if (i >= NTOTAL) return;
    if (i >= NCHUNK) {
        size_t j = i - NCHUNK;
        int l = (int)(j / 768), r = (int)(j % 768);
        float4 s;
        if (r < 256)       s = bq[l*256 + r];
        else if (r < 512)  s = bk[l*256 + (r-256)];
        else               s = bv[l*256 + (r-512)];
        bqkv[j] = s;
        return;
    }
    float4 v;
    __nv_bfloat162* base;
    size_t dst;
    if (i < CW) {
        size_t l = i / CPL, r = i % CPL;
        v = Wq[i]; base = qkv; dst = l*QPL + r;
    } else if (i < 2*CW) {
        size_t j = i - CW, l = j / CPL, r = j % CPL;
        v = Wk[j]; base = qkv; dst = l*QPL + CPL + r;
    } else if (i < 3*CW) {
        size_t j = i - 2*CW, l = j / CPL, r = j % CPL;
        v = Wv[j]; base = qkv; dst = l*QPL + 2*CPL + r;
    } else if (i < 4*CW) {
        size_t j = i - 3*CW; v = Wo[j]; base = wo; dst = j;
    } else if (i < 4*CW + CFF) {
        size_t j = i - 4*CW; v = W1[j]; base = w1; dst = j;
    } else if (i < 4*CW + 2*CFF) {
        size_t j = i - 4*CW - CFF; v = W2[j]; base = w2; dst = j;
    } else {
        size_t j = i - 4*CW - 2*CFF; v = fcW[j]; base = fc; dst = j;
    }
    base[2*dst]   = __floats2bfloat162_rn(v.x, v.y);
    base[2*dst+1] = __floats2bfloat162_rn(v.z, v.w);
}

// ---------------- embedding (float4) + output zeroing --------------------------
__global__ void embed_kernel(const int* __restrict__ tokens,
                             const float4* __restrict__ emb,
                             const float4* __restrict__ pe,
                             float4* __restrict__ x,
                             float* __restrict__ out)
{
    int idx = blockIdx.x * blockDim.x + threadIdx.x;
    if (blockIdx.x == 0 && threadIdx.x < Bv) out[threadIdx.x] = 0.f;
    if (idx >= Mv*Dv/4) return;
    int d4 = idx & 255;
    int ms = idx >> 8;
    int s  = ms & (Sv-1);
    int t  = tokens[ms];
    float4 e = emb[(size_t)t*256 + d4];
    float4 p = pe[(size_t)s*256 + d4];
    float4 o;
    o.x = e.x*32.0f + p.x; o.y = e.y*32.0f + p.y;
    o.z = e.z*32.0f + p.z; o.w = e.w*32.0f + p.w;
    x[idx] = o;
}

// ---------------- layernorm (single global read, float4) ----------------------
__global__ __launch_bounds__(256) void ln_kernel(const float* __restrict__ x,
                                                 const float* __restrict__ g,
                                                 const float* __restrict__ b,
                                                 __nv_bfloat16* __restrict__ out)
{
    __shared__ float sred[2][8];
    int row = blockIdx.x, tid = threadIdx.x;
    float4 v = ((const float4*)(x + (size_t)row * Dv))[tid];
    float s  = v.x + v.y + v.z + v.w;
    float s2 = v.x*v.x + v.y*v.y + v.z*v.z + v.w*v.w;
    #pragma unroll
    for (int o = 16; o; o >>= 1) {
        s  += __shfl_xor_sync(0xffffffffu, s,  o);
        s2 += __shfl_xor_sync(0xffffffffu, s2, o);
    }
    int w = tid >> 5;
    if ((tid & 31) == 0) { sred[0][w] = s; sred[1][w] = s2; }
    __syncthreads();
    if (tid < 32) {
        s  = (tid < 8) ? sred[0][tid] : 0.f;
        s2 = (tid < 8) ? sred[1][tid] : 0.f;
        #pragma unroll
        for (int o = 4; o; o >>= 1) {
            s  += __shfl_xor_sync(0xffffffffu, s,  o);
            s2 += __shfl_xor_sync(0xffffffffu, s2, o);
        }
        if (tid == 0) { sred[0][0] = s; sred[1][0] = s2; }
    }
    __syncthreads();
    float mu  = sred[0][0] * (1.0f/Dv);
    float var = sred[1][0] * (1.0f/Dv) - mu*mu;
    float inv = rsqrtf(var + 1e-5f);
    float4 gg = ((const float4*)g)[tid];
    float4 bb = ((const float4*)b)[tid];
    float r0 = (v.x-mu)*inv*gg.x + bb.x;
    float r1 = (v.y-mu)*inv*gg.y + bb.y;
    float r2 = (v.z-mu)*inv*gg.z + bb.z;
    float r3 = (v.w-mu)*inv*gg.w + bb.w;
    __nv_bfloat162 p0 = __floats2bfloat162_rn(r0, r1);
    __nv_bfloat162 p1 = __floats2bfloat162_rn(r2, r3);
    uint2 pk; pk.x = *(uint32_t*)&p0; pk.y = *(uint32_t*)&p1;
    ((uint2*)(out + (size_t)row * Dv))[tid] = pk;
}

// ---------------- MMA helpers -------------------------------------------------
__device__ __forceinline__ void cp16(void* s, const void* g) {
    uint32_t sa = (uint32_t)__cvta_generic_to_shared(s);
    asm volatile("cp.async.cg.shared.global [%0], [%1], 16;\n" :: "r"(sa), "l"(g));
}
__device__ __forceinline__ void ldsm4(uint32_t* r, const void* p) {
    uint32_t a = (uint32_t)__cvta_generic_to_shared(p);
    asm volatile("ldmatrix.sync.aligned.m8n8.x4.shared.b16 {%0,%1,%2,%3}, [%4];"
        : "=r"(r[0]), "=r"(r[1]), "=r"(r[2]), "=r"(r[3]) : "r"(a));
}
__device__ __forceinline__ void ldsm4t(uint32_t* r, const void* p) {
    uint32_t a = (uint32_t)__cvta_generic_to_shared(p);
    asm volatile("ldmatrix.sync.aligned.m8n8.x4.trans.shared.b16 {%0,%1,%2,%3}, [%4];"
        : "=r"(r[0]), "=r"(r[1]), "=r"(r[2]), "=r"(r[3]) : "r"(a));
}
__device__ __forceinline__ void mma16816(float* c, const uint32_t* a, const uint32_t* b) {
    asm volatile("mma.sync.aligned.m16n8k16.row.col.f32.bf16.bf16.f32 "
        "{%0,%1,%2,%3}, {%4,%5,%6,%7}, {%8,%9}, {%0,%1,%2,%3};"
        : "+f"(c[0]), "+f"(c[1]), "+f"(c[2]), "+f"(c[3])
        : "r"(a[0]), "r"(a[1]), "r"(a[2]), "r"(a[3]), "r"(b[0]), "r"(b[1]));
}

// ---------------- bf16 tensor-core GEMM: 128x128, GBK=64, 3-stage, 2 CTA/SM ---
// warp tile 64x32 (8 warps), 4 K=16 sub-steps per stage (round-13 proven config)
// mode 0: ->f32   1: GELU->bf16   2: +res->f32   3: ->bf16
#define GBM 128
#define GBN 128
#define GBK 64
#define PADK 72
#define STAGES 3
#define SMEM_G (STAGES * (GBM + GBN) * PADK * 2)    // 110592 B

__global__ __launch_bounds__(256, 2) void hgemm_kernel(
    const __nv_bfloat16* __restrict__ A, const __nv_bfloat16* __restrict__ Bw,
    const float* __restrict__ bias, const float* __restrict__ res,
    void* __restrict__ Cc, int Mr, int Nr, int Kr, int mode)
{
    extern __shared__ __nv_bfloat16 sm[];
    __nv_bfloat16* As = sm;
    __nv_bfloat16* Bs = sm + STAGES * GBM * PADK;

    int tid  = threadIdx.x;
    int warp = tid >> 5;
    int lane = tid & 31;
    int warp_m = warp & 1;
    int warp_n = warp >> 1;
    int row0 = blockIdx.y * GBM;
    int col0 = blockIdx.x * GBN;

    float acc[4][4][4];
    #pragma unroll
    for (int i = 0; i < 4; i++)
        #pragma unroll
        for (int j = 0; j < 4; j++)
            #pragma unroll
            for (int t = 0; t < 4; t++) acc[i][j][t] = 0.f;

    const __nv_bfloat16* Ab = A  + (size_t)row0 * Kr;
    const __nv_bfloat16* Bb = Bw + (size_t)col0 * Kr;
    int kt_total = Kr / GBK;

    auto load_stage = [&](int st, int kb) {
        __nv_bfloat16* as = As + st * GBM * PADK;
        __nv_bfloat16* bs = Bs + st * GBN * PADK;
        #pragma unroll
        for (int c = 0; c < 4; c++) {
            int idx = tid + c*256;
            int r = idx >> 3, kk = (idx & 7) * 8;
            cp16(&as[r*PADK + kk], Ab + (size_t)r*Kr + kb + kk);
            cp16(&bs[r*PADK + kk], Bb + (size_t)r*Kr + kb + kk);
        }
    };

    #pragma unroll
    for (int s = 0; s < STAGES-1; s++) {
        if (s < kt_total) load_stage(s, s*GBK);
        asm volatile("cp.async.commit_group;\n" ::: "memory");
    }

    for (int kt = 0; kt < kt_total; kt++) {
        asm volatile("cp.async.wait_group %0;\n" :: "n"(STAGES-2) : "memory");
        __syncthreads();

        int nk = kt + STAGES - 1;
        if (nk < kt_total) load_stage(nk % STAGES, nk*GBK);
        asm volatile("cp.async.commit_group;\n" ::: "memory");

        const __nv_bfloat16* as = As + (kt % STAGES) * GBM * PADK;
        const __nv_bfloat16* bs = Bs + (kt % STAGES) * GBN * PADK;

        #pragma unroll
        for (int ks = 0; ks < 4; ks++) {
            int kof = ks * 16;
            uint32_t ra[4][4];
            #pragma unroll
            for (int mi = 0; mi < 4; mi++) {
                int rr = warp_m*64 + mi*16 + (lane & 15);
                ldsm4(ra[mi], as + rr*PADK + kof + (lane >> 4)*8);
            }
            uint32_t rb[2][4];
            #pragma unroll
            for (int nj = 0; nj < 2; nj++) {
                int nn = warp_n*32 + nj*16 + (lane & 7) + ((lane & 16) >> 1);
                ldsm4(rb[nj], bs + nn*PADK + kof + ((lane >> 3) & 1)*8);
            }
            #pragma unroll
            for (int mi = 0; mi < 4; mi++)
                #pragma unroll
                for (int nt = 0; nt < 4; nt++)
                    mma16816(acc[mi][nt], ra[mi], &rb[nt >> 1][(nt & 1)*2]);
        }
    }

    #pragma unroll
    for (int mi = 0; mi < 4; mi++) {
        int rw = row0 + warp_m*64 + mi*16 + (lane >> 2);
        #pragma unroll
        for (int nt = 0; nt < 4; nt++) {
            int cw = col0 + warp_n*32 + nt*8 + (lane & 3)*2;
            float2 bb = *(const float2*)(bias + cw);
            float v0 = acc[mi][nt][0] + bb.x;
            float v1 = acc[mi][nt][1] + bb.y;
            float v2 = acc[mi][nt][2] + bb.x;
            float v3 = acc[mi][nt][3] + bb.y;
            if (mode == 0) {
                float* C = (float*)Cc;
                *(float2*)(C + (size_t)rw*Nr + cw)     = make_float2(v0, v1);
                *(float2*)(C + (size_t)(rw+8)*Nr + cw) = make_float2(v2, v3);
            } else if (mode == 1) {
                v0 = v0 * normcdff(v0); v1 = v1 * normcdff(v1);
                v2 = v2 * normcdff(v2); v3 = v3 * normcdff(v3);
                __nv_bfloat16* C = (__nv_bfloat16*)Cc;
                *(__nv_bfloat162*)(C + (size_t)rw*Nr + cw)     = __floats2bfloat162_rn(v0, v1);
                *(__nv_bfloat162*)(C + (size_t)(rw+8)*Nr + cw) = __floats2bfloat162_rn(v2, v3);
            } else if (mode == 2) {
                float* C = (float*)Cc;
                float2 r1 = *(const float2*)(res + (size_t)rw*Nr + cw);
                float2 r2 = *(const float2*)(res + (size_t)(rw+8)*Nr + cw);
                *(float2*)(C + (size_t)rw*Nr + cw)     = make_float2(v0 + r1.x, v1 + r1.y);
                *(float2*)(C + (size_t)(rw+8)*Nr + cw) = make_float2(v2 + r2.x, v3 + r2.y);
            } else {
                __nv_bfloat16* C = (__nv_bfloat16*)Cc;
                *(__nv_bfloat162*)(C + (size_t)rw*Nr + cw)     = __floats2bfloat162_rn(v0, v1);
                *(__nv_bfloat162*)(C + (size_t)(rw+8)*Nr + cw) = __floats2bfloat162_rn(v2, v3);
            }
        }
    }
}

// ---------------- MMA flash attention: 128 queries/block, 128-key smem tiles --
// compute runs in two 64-key sub-iterations (same regs); barriers/fills halved
#define AQ 128
#define AKB 128
#define APAD 72

__global__ __launch_bounds__(256) void attn_mma_kernel(
    const __nv_bfloat16* __restrict__ q, const __nv_bfloat16* __restrict__ k,
    const __nv_bfloat16* __restrict__ v, __nv_bfloat16* __restrict__ y)
{
    __shared__ __nv_bfloat16 Qs[AQ][APAD];
    __shared__ __nv_bfloat16 Ks[AKB][APAD];
    __shared__ __nv_bfloat16 Vs[AKB][APAD];

    int b = blockIdx.z, h = blockIdx.y;
    int q0 = blockIdx.x * AQ;
    int tid = threadIdx.x, wid = tid >> 5, lane = tid & 31;

    {
        int row = tid >> 1, half = (tid & 1) * 32;
        const uint4* src = (const uint4*)(q + ((size_t)(b*Sv + q0 + row))*QKVS + h*HDv + half);
        uint4* dst = (uint4*)&Qs[row][half];
        dst[0] = src[0]; dst[1] = src[1]; dst[2] = src[2]; dst[3] = src[3];
    }

    float m0 = -1e30f, m1 = -1e30f, l0 = 0.f, l1 = 0.f;
    float Oa[8][4];
    #pragma unroll
    for (int i = 0; i < 8; i++)
        #pragma unroll
        for (int j = 0; j < 4; j++) Oa[i][j] = 0.f;

    int r_lo = lane >> 2;
    int colb = (lane & 3) * 2;
    int wrow_max = q0 + wid*16 + 15;

    for (int j0 = 0; j0 <= q0; j0 += AKB) {
        __syncthreads();
        {   // fill 128-key K/V tiles: 128 rows x 8 chunks(16B); 4 chunks/thread
            #pragma unroll
            for (int c = 0; c < 4; c++) {
                int idx = tid + c*256;
                int row = idx >> 3, col = (idx & 7) * 8;
                size_t off = ((size_t)(b*Sv + j0 + row))*QKVS + h*HDv + col;
                *(uint4*)&Ks[row][col] = *(const uint4*)(k + off);
                *(uint4*)&Vs[row][col] = *(const uint4*)(v + off);
            }
        }
        __syncthreads();

        #pragma unroll
        for (int sub = 0; sub < 2; sub++) {
            int jb = j0 + sub*64;
            if (jb > wrow_max) break;       // no barriers inside: safe per-warp exit
            int kro = sub*64;               // smem row offset for this sub-tile

            float c[8][4];
            #pragma unroll
            for (int i = 0; i < 8; i++)
                #pragma unroll
                for (int j = 0; j < 4; j++) c[i][j] = 0.f;

            #pragma unroll
            for (int kk = 0; kk < 4; kk++) {
                int kof = kk * 16;
                uint32_t ra[4];
                ldsm4(ra, &Qs[wid*16 + (lane & 15)][kof + (lane >> 4)*8]);
                #pragma unroll
                for (int nt = 0; nt < 4; nt++) {
                    uint32_t rb[4];
                    int nn = kro + nt*16 + (lane & 7) + ((lane & 16) >> 1);
                    ldsm4(rb, &Ks[nn][kof + ((lane >> 3) & 1)*8]);
                    mma16816(c[2*nt],   ra, &rb[0]);
                    mma16816(c[2*nt+1], ra, &rb[2]);
                }
            }

            int row0 = q0 + wid*16 + r_lo;
            int row1 = row0 + 8;
            #pragma unroll
            for (int nt = 0; nt < 8; nt++) {
                c[nt][0] *= 0.125f; c[nt][1] *= 0.125f;
                c[nt][2] *= 0.125f; c[nt][3] *= 0.125f;
            }
            if (jb + 63 > row0) {
                #pragma unroll
                for (int nt = 0; nt < 8; nt++) {
                    int col = jb + nt*8 + colb;
                    if (col   > row0) c[nt][0] = -1e30f;
                    if (col+1 > row0) c[nt][1] = -1e30f;
                    if (col   > row1) c[nt][2] = -1e30f;
                    if (col+1 > row1) c[nt][3] = -1e30f;
                }
            }

            float rm0 = -1e30f, rm1 = -1e30f;
            #pragma unroll
            for (int nt = 0; nt < 8; nt++) {
                rm0 = fmaxf(rm0, fmaxf(c[nt][0], c[nt][1]));
                rm1 = fmaxf(rm1, fmaxf(c[nt][2], c[nt][3]));
            }
            rm0 = fmaxf(rm0, __shfl_xor_sync(0xffffffffu, rm0, 1));
            rm0 = fmaxf(rm0, __shfl_xor_sync(0xffffffffu, rm0, 2));
            rm1 = fmaxf(rm1, __shfl_xor_sync(0xffffffffu, rm1, 1));
            rm1 = fmaxf(rm1, __shfl_xor_sync(0xffffffffu, rm1, 2));

            float mn0 = fmaxf(m0, rm0), mn1 = fmaxf(m1, rm1);
            float cr0 = __expf(m0 - mn0), cr1 = __expf(m1 - mn1);
            m0 = mn0; m1 = mn1;

            float ps0 = 0.f, ps1 = 0.f;
            #pragma unroll
            for (int nt = 0; nt < 8; nt++) {
                c[nt][0] = __expf(c[nt][0] - mn0);
                c[nt][1] = __expf(c[nt][1] - mn0);
                c[nt][2] = __expf(c[nt][2] - mn1);
                c[nt][3] = __expf(c[nt][3] - mn1);
                ps0 += c[nt][0] + c[nt][1];
                ps1 += c[nt][2] + c[nt][3];
            }
            ps0 += __shfl_xor_sync(0xffffffffu, ps0, 1);
            ps0 += __shfl_xor_sync(0xffffffffu, ps0, 2);
            ps1 += __shfl_xor_sync(0xffffffffu, ps1, 1);
            ps1 += __shfl_xor_sync(0xffffffffu, ps1, 2);
            l0 = l0*cr0 + ps0;
            l1 = l1*cr1 + ps1;

            #pragma unroll
            for (int nt = 0; nt < 8; nt++) {
                Oa[nt][0] *= cr0; Oa[nt][1] *= cr0;
                Oa[nt][2] *= cr1; Oa[nt][3] *= cr1;
            }

            #pragma unroll
            for (int kt = 0; kt < 4; kt++) {
                uint32_t a[4];
                __nv_bfloat162 p0 = __floats2bfloat162_rn(c[2*kt][0],   c[2*kt][1]);
                __nv_bfloat162 p1 = __floats2bfloat162_rn(c[2*kt][2],   c[2*kt][3]);
                __nv_bfloat162 p2 = __floats2bfloat162_rn(c[2*kt+1][0], c[2*kt+1][1]);
                __nv_bfloat162 p3 = __floats2bfloat162_rn(c[2*kt+1][2], c[2*kt+1][3]);
                a[0] = *(uint32_t*)&p0; a[1] = *(uint32_t*)&p1;
                a[2] = *(uint32_t*)&p2; a[3] = *(uint32_t*)&p3;
                #pragma unroll
                for (int nt = 0; nt < 4; nt++) {
                    uint32_t rv[4];
                    int key = kro + kt*16 + (lane & 7) + ((lane >> 3) & 1)*8;
                    int dim = nt*16 + (lane >> 4)*8;
                    ldsm4t(rv, &Vs[key][dim]);
                    mma16816(Oa[2*nt],   a, &rv[0]);
                    mma16816(Oa[2*nt+1], a, &rv[2]);
                }
            }
        }
    }

    float il0 = 1.0f / l0, il1 = 1.0f / l1;
    int grow0 = q0 + wid*16 + r_lo;
    #pragma unroll
    for (int nt = 0; nt < 8; nt++) {
        int dcol = nt*8 + colb;
        __nv_bfloat16* yp0 = y + ((size_t)(b*Sv + grow0))*Dv + h*HDv + dcol;
        __nv_bfloat16* yp1 = y + ((size_t)(b*Sv + grow0 + 8))*Dv + h*HDv + dcol;
        *(__nv_bfloat162*)yp0 = __floats2bfloat162_rn(Oa[nt][0]*il0, Oa[nt][1]*il0);
        *(__nv_bfloat162*)yp1 = __floats2bfloat162_rn(Oa[nt][2]*il1, Oa[nt][3]*il1);
    }
}

// ---------------- final loss (bf16 logits, single-pass online softmax) --------
__global__ __launch_bounds__(256) void loss_kernel(const __nv_bfloat16* __restrict__ logits,
                                                   const int* __restrict__ tokens,
                                                   float* __restrict__ out)
{
    __shared__ float smax[8], ssum[8];
    int row = blockIdx.x, tid = threadIdx.x;
    const uint4* lr8 = (const uint4*)(logits + (size_t)row * Cv);

    float m = -1e30f, s = 0.f;
    #pragma unroll
    for (int c = 0; c < Cv/2048; c++) {
        uint4 u = lr8[tid + c*256];
        float2 f0 = __bfloat1622float2(*(__nv_bfloat162*)&u.x);
        float2 f1 = __bfloat1622float2(*(__nv_bfloat162*)&u.y);
        float2 f2 = __bfloat1622float2(*(__nv_bfloat162*)&u.z);
        float2 f3 = __bfloat1622float2(*(__nv_bfloat162*)&u.w);
        float vm = fmaxf(fmaxf(fmaxf(f0.x, f0.y), fmaxf(f1.x, f1.y)),
                         fmaxf(fmaxf(f2.x, f2.y), fmaxf(f3.x, f3.y)));
        if (vm > m) { s = s * __expf(m - vm); m = vm; }
        s += __expf(f0.x - m) + __expf(f0.y - m) + __expf(f1.x - m) + __expf(f1.y - m)
           + __expf(f2.x - m) + __expf(f2.y - m) + __expf(f3.x - m) + __expf(f3.y - m);
    }
    #pragma unroll
    for (int o = 16; o; o >>= 1) {
        float m2 = __shfl_xor_sync(0xffffffffu, m, o);
        float s2 = __shfl_xor_sync(0xffffffffu, s, o);
        float mn = fmaxf(m, m2);
        s = s * __expf(m - mn) + s2 * __expf(m2 - mn);
        m = mn;
    }
    int w = tid >> 5;
    if ((tid & 31) == 0) { smax[w] = m; ssum[w] = s; }
    __syncthreads();
    if (tid == 0) {
        m = smax[0]; s = ssum[0];
        #pragma unroll
        for (int i = 1; i < 8; i++) {
            float mn = fmaxf(m, smax[i]);
            s = s * __expf(m - mn) + ssum[i] * __expf(smax[i] - mn);
            m = mn;
        }
        int t = tokens[row];
        if (t != PADTOK) {
            float lt = __bfloat162float(logits[(size_t)row * Cv + t]);
            float lp = lt - m - logf(s);
            atomicAdd(&out[row / Sv], lp);
        }
    }
}

// ---------------- driver -----------------------------------------------------
static void run_hgemm(const __nv_bfloat16* A, const __nv_bfloat16* W,
                      const float* bias, const float* res,
                      void* Cc, int M_, int N_, int K_, int mode)
{
    dim3 grid(N_/GBN, M_/GBM);
    hgemm_kernel<<<grid, 256, SMEM_G>>>(A, W, bias, res, Cc, M_, N_, K_, mode);
}

extern "C" void kernel_launch(void* const* d_in, const int* in_sizes, int n_in,
                              void* d_out, int out_size)
{
    const int*   tokens = (const int*)  d_in[0];
    const float* emb    = (const float*)d_in[1];
    const float* pe     = (const float*)d_in[2];
    const float* ln1_g  = (const float*)d_in[3];
    const float* ln1_b  = (const float*)d_in[4];
    const float* Wq     = (const float*)d_in[5];
    const float* bq     = (const float*)d_in[6];
    const float* Wk     = (const float*)d_in[7];
    const float* bk     = (const float*)d_in[8];
    const float* Wv     = (const float*)d_in[9];
    const float* bv     = (const float*)d_in[10];
    const float* Wo     = (const float*)d_in[11];
    const float* bo     = (const float*)d_in[12];
    const float* ln2_g  = (const float*)d_in[13];
    const float* ln2_b  = (const float*)d_in[14];
    const float* W1     = (const float*)d_in[15];
    const float* b1     = (const float*)d_in[16];
    const float* W2     = (const float*)d_in[17];
    const float* b2     = (const float*)d_in[18];
    const float* lnf_g  = (const float*)d_in[19];
    const float* lnf_b  = (const float*)d_in[20];
    const float* fcW    = (const float*)d_in[21];
    const float* fcb    = (const float*)d_in[22];
    float* out = (float*)d_out;

    cudaFuncSetAttribute(hgemm_kernel, cudaFuncAttributeMaxDynamicSharedMemorySize, SMEM_G);

    float *x, *bqkv;
    __nv_bfloat16 *h, *y, *ff, *qkv, *logits;
    __nv_bfloat16 *wqkv, *wo_b, *w1_b, *w2_b, *fcw_b;
    cudaGetSymbolAddress((void**)&x,    g_x);
    cudaGetSymbolAddress((void**)&h,    g_h);
    cudaGetSymbolAddress((void**)&qkv,  g_qkv);
    cudaGetSymbolAddress((void**)&y,    g_y);
    cudaGetSymbolAddress((void**)&ff,   g_ff);
    cudaGetSymbolAddress((void**)&logits, g_logits);
    cudaGetSymbolAddress((void**)&wqkv, g_Wqkv);
    cudaGetSymbolAddress((void**)&bqkv, g_bqkv);
    cudaGetSymbolAddress((void**)&wo_b, g_Wo);
    cudaGetSymbolAddress((void**)&w1_b, g_W1);
    cudaGetSymbolAddress((void**)&w2_b, g_W2);
    cudaGetSymbolAddress((void**)&fcw_b, g_fcW);

    conv_all_kernel<<<(unsigned)((NTOTAL + 255)/256), 256>>>(
        (const float4*)Wq, (const float4*)Wk, (const float4*)Wv,
        (const float4*)Wo, (const float4*)W1, (const float4*)W2, (const float4*)fcW,
        (const float4*)bq, (const float4*)bk, (const float4*)bv, (float4*)bqkv,
        (__nv_bfloat162*)wqkv, (__nv_bfloat162*)wo_b,
        (__nv_bfloat162*)w1_b, (__nv_bfloat162*)w2_b, (__nv_bfloat162*)fcw_b);
    embed_kernel<<<(Mv*Dv/4 + 255)/256, 256>>>(tokens, (const float4*)emb,
                                               (const float4*)pe, (float4*)x, out);

    for (int i = 0; i < Lv; i++) {
        const __nv_bfloat16* wl  = wqkv + (size_t)i*QKVS*Dv;
        const float*         bl  = bqkv + (size_t)i*QKVS;
        const __nv_bfloat16* wo  = wo_b + (size_t)i*Dv*Dv;
        const __nv_bfloat16* w1  = w1_b + (size_t)i*FFv*Dv;
        const __nv_bfloat16* w2  = w2_b + (size_t)i*Dv*FFv;

        ln_kernel<<<Mv, 256>>>(x, ln1_g + i*Dv, ln1_b + i*Dv, h);
        run_hgemm(h, wl, bl, nullptr, qkv, Mv, QKVS, Dv, 3);

        dim3 agrid(Sv/AQ, Hv, Bv);
        attn_mma_kernel<<<agrid, 256>>>(qkv, qkv + Dv, qkv + 2*Dv, y);

        run_hgemm(y, wo, bo + i*Dv, x, x, Mv, Dv, Dv, 2);

        ln_kernel<<<Mv, 256>>>(x, ln2_g + i*Dv, ln2_b + i*Dv, h);
        run_hgemm(h, w1, b1 + i*FFv, nullptr, ff, Mv, FFv, Dv, 1);
        run_hgemm(ff, w2, b2 + i*Dv, x, x, Mv, Dv, FFv, 2);
    }

    ln_kernel<<<Mv, 256>>>(x, lnf_g, lnf_b, h);
    run_hgemm(h, fcw_b, fcb, nullptr, logits, Mv, Cv, Dv, 3);

    loss_kernel<<<Mv, 256>>>(logits, tokens, out);
}

// round 17
// speedup vs baseline: 1.0494x; 1.0034x over previous
#include <cuda_runtime.h>
#include <cuda_bf16.h>
#include <math.h>
#include <stdint.h>

#define Bv 4
#define Sv 1024
#define Dv 1024
#define Hv 16
#define Lv 12
#define Cv 8192
#define FFv 4096
#define HDv 64
#define Mv (Bv*Sv)
#define PADTOK 2
#define QKVS (3*Dv)

// ---------------- scratch ----------------------------------------------------
__device__ float g_x[Mv*Dv];
__device__ __nv_bfloat16 g_h[Mv*Dv];
__device__ __nv_bfloat16 g_qkv[(size_t)Mv*QKVS];
__device__ __nv_bfloat16 g_y[Mv*Dv];
__device__ __nv_bfloat16 g_ff[(size_t)Mv*FFv];
__device__ __nv_bfloat16 g_logits[(size_t)Mv*Cv];

__device__ __nv_bfloat16 g_Wqkv[(size_t)Lv*QKVS*Dv];
__device__ float         g_bqkv[(size_t)Lv*QKVS];
__device__ __nv_bfloat16 g_Wo[(size_t)Lv*Dv*Dv];
__device__ __nv_bfloat16 g_W1[(size_t)Lv*FFv*Dv];
__device__ __nv_bfloat16 g_W2[(size_t)Lv*Dv*FFv];
__device__ __nv_bfloat16 g_fcW[(size_t)Cv*Dv];

// ---------------- fused weight conversion + bias packing ----------------------
#define CW  3145728ULL
#define CFF 12582912ULL
#define CFC 2097152ULL
#define CPL 262144ULL
#define QPL 786432ULL
#define NCHUNK (4ULL*CW + 2ULL*CFF + CFC)
#define NBIAS  ((size_t)Lv*QKVS/4)
#define NTOTAL (NCHUNK + NBIAS)

__global__ __launch_bounds__(256) void conv_all_kernel(
    const float4* __restrict__ Wq, const float4* __restrict__ Wk,
    const float4* __restrict__ Wv, const float4* __restrict__ Wo,
    const float4* __restrict__ W1, const float4* __restrict__ W2,
    const float4* __restrict__ fcW,
    const float4* __restrict__ bq, const float4* __restrict__ bk,
    const float4* __restrict__ bv, float4* __restrict__ bqkv,
    __nv_bfloat162* __restrict__ qkv, __nv_bfloat162* __restrict__ wo,
    __nv_bfloat162* __restrict__ w1,  __nv_bfloat162* __restrict__ w2,
    __nv_bfloat162* __restrict__ fc)
{
    size_t i = (size_t)blockIdx.x * 256 + threadIdx.x;
    if (i >= NTOTAL) return;
    if (i >= NCHUNK) {
        size_t j = i - NCHUNK;
        int l = (int)(j / 768), r = (int)(j % 768);
        float4 s;
        if (r < 256)       s = bq[l*256 + r];
        else if (r < 512)  s = bk[l*256 + (r-256)];
        else               s = bv[l*256 + (r-512)];
        bqkv[j] = s;
        return;
    }
    float4 v;
    __nv_bfloat162* base;
    size_t dst;
    if (i < CW) {
        size_t l = i / CPL, r = i % CPL;
        v = Wq[i]; base = qkv; dst = l*QPL + r;
    } else if (i < 2*CW) {
        size_t j = i - CW, l = j / CPL, r = j % CPL;
        v = Wk[j]; base = qkv; dst = l*QPL + CPL + r;
    } else if (i < 3*CW) {
        size_t j = i - 2*CW, l = j / CPL, r = j % CPL;
        v = Wv[j]; base = qkv; dst = l*QPL + 2*CPL + r;
    } else if (i < 4*CW) {
        size_t j = i - 3*CW; v = Wo[j]; base = wo; dst = j;
    } else if (i < 4*CW + CFF) {
        size_t j = i - 4*CW; v = W1[j]; base = w1; dst = j;
    } else if (i < 4*CW + 2*CFF) {
        size_t j = i - 4*CW - CFF; v = W2[j]; base = w2; dst = j;
    } else {
        size_t j = i - 4*CW - 2*CFF; v = fcW[j]; base = fc; dst = j;
    }
    base[2*dst]   = __floats2bfloat162_rn(v.x, v.y);
    base[2*dst+1] = __floats2bfloat162_rn(v.z, v.w);
}

// ---------------- embedding (float4) + output zeroing --------------------------
__global__ void embed_kernel(const int* __restrict__ tokens,
                             const float4* __restrict__ emb,
                             const float4* __restrict__ pe,
                             float4* __restrict__ x,
                             float* __restrict__ out)
{
    int idx = blockIdx.x * blockDim.x + threadIdx.x;
    if (blockIdx.x == 0 && threadIdx.x < Bv) out[threadIdx.x] = 0.f;
    if (idx >= Mv*Dv/4) return;
    int d4 = idx & 255;
    int ms = idx >> 8;
    int s  = ms & (Sv-1);
    int t  = tokens[ms];
    float4 e = emb[(size_t)t*256 + d4];
    float4 p = pe[(size_t)s*256 + d4];
    float4 o;
    o.x = e.x*32.0f + p.x; o.y = e.y*32.0f + p.y;
    o.z = e.z*32.0f + p.z; o.w = e.w*32.0f + p.w;
    x[idx] = o;
}

// ---------------- layernorm: warp-per-row, 8 rows/block ------------------------
__global__ __launch_bounds__(256) void ln_kernel(const float* __restrict__ x,
                                                 const float* __restrict__ g,
                                                 const float* __restrict__ b,
                                                 __nv_bfloat16* __restrict__ out)
{
    int warp = threadIdx.x >> 5, lane = threadIdx.x & 31;
    int row  = blockIdx.x * 8 + warp;
    const float4* xr = (const float4*)(x + (size_t)row * Dv);

    float4 v[8];
    float s = 0.f, s2 = 0.f;
    #pragma unroll
    for (int i = 0; i < 8; i++) {
        v[i] = xr[lane + i*32];
        s  += v[i].x + v[i].y + v[i].z + v[i].w;
        s2 += v[i].x*v[i].x + v[i].y*v[i].y + v[i].z*v[i].z + v[i].w*v[i].w;
    }
    #pragma unroll
    for (int o = 16; o; o >>= 1) {
        s  += __shfl_xor_sync(0xffffffffu, s,  o);
        s2 += __shfl_xor_sync(0xffffffffu, s2, o);
    }
    float mu  = s  * (1.0f/Dv);
    float var = s2 * (1.0f/Dv) - mu*mu;
    float inv = rsqrtf(var + 1e-5f);

    uint2* orow = (uint2*)(out + (size_t)row * Dv);
    #pragma unroll
    for (int i = 0; i < 8; i++) {
        float4 gg = ((const float4*)g)[lane + i*32];
        float4 bb = ((const float4*)b)[lane + i*32];
        float r0 = (v[i].x-mu)*inv*gg.x + bb.x;
        float r1 = (v[i].y-mu)*inv*gg.y + bb.y;
        float r2 = (v[i].z-mu)*inv*gg.z + bb.z;
        float r3 = (v[i].w-mu)*inv*gg.w + bb.w;
        __nv_bfloat162 p0 = __floats2bfloat162_rn(r0, r1);
        __nv_bfloat162 p1 = __floats2bfloat162_rn(r2, r3);
        uint2 pk; pk.x = *(uint32_t*)&p0; pk.y = *(uint32_t*)&p1;
        orow[lane + i*32] = pk;
    }
}

// ---------------- MMA helpers -------------------------------------------------
__device__ __forceinline__ void cp16(void* s, const void* g) {
    uint32_t sa = (uint32_t)__cvta_generic_to_shared(s);
    asm volatile("cp.async.cg.shared.global [%0], [%1], 16;\n" :: "r"(sa), "l"(g));
}
__device__ __forceinline__ void ldsm4(uint32_t* r, const void* p) {
    uint32_t a = (uint32_t)__cvta_generic_to_shared(p);
    asm volatile("ldmatrix.sync.aligned.m8n8.x4.shared.b16 {%0,%1,%2,%3}, [%4];"
        : "=r"(r[0]), "=r"(r[1]), "=r"(r[2]), "=r"(r[3]) : "r"(a));
}
__device__ __forceinline__ void ldsm4t(uint32_t* r, const void* p) {
    uint32_t a = (uint32_t)__cvta_generic_to_shared(p);
    asm volatile("ldmatrix.sync.aligned.m8n8.x4.trans.shared.b16 {%0,%1,%2,%3}, [%4];"
        : "=r"(r[0]), "=r"(r[1]), "=r"(r[2]), "=r"(r[3]) : "r"(a));
}
__device__ __forceinline__ void mma16816(float* c, const uint32_t* a, const uint32_t* b) {
    asm volatile("mma.sync.aligned.m16n8k16.row.col.f32.bf16.bf16.f32 "
        "{%0,%1,%2,%3}, {%4,%5,%6,%7}, {%8,%9}, {%0,%1,%2,%3};"
        : "+f"(c[0]), "+f"(c[1]), "+f"(c[2]), "+f"(c[3])
        : "r"(a[0]), "r"(a[1]), "r"(a[2]), "r"(a[3]), "r"(b[0]), "r"(b[1]));
}

// ---------------- bf16 tensor-core GEMM: 128x128, GBK=64, 3-stage, 2 CTA/SM ---
// warp tile 64x32 (8 warps), 4 K=16 sub-steps per stage (round-13 proven config)
// mode 0: ->f32   1: GELU->bf16   2: +res->f32   3: ->bf16
#define GBM 128
#define GBN 128
#define GBK 64
#define PADK 72
#define STAGES 3
#define SMEM_G (STAGES * (GBM + GBN) * PADK * 2)    // 110592 B

__global__ __launch_bounds__(256, 2) void hgemm_kernel(
    const __nv_bfloat16* __restrict__ A, const __nv_bfloat16* __restrict__ Bw,
    const float* __restrict__ bias, const float* __restrict__ res,
    void* __restrict__ Cc, int Mr, int Nr, int Kr, int mode)
{
    extern __shared__ __nv_bfloat16 sm[];
    __nv_bfloat16* As = sm;
    __nv_bfloat16* Bs = sm + STAGES * GBM * PADK;

    int tid  = threadIdx.x;
    int warp = tid >> 5;
    int lane = tid & 31;
    int warp_m = warp & 1;
    int warp_n = warp >> 1;
    int row0 = blockIdx.y * GBM;
    int col0 = blockIdx.x * GBN;

    float acc[4][4][4];
    #pragma unroll
    for (int i = 0; i < 4; i++)
        #pragma unroll
        for (int j = 0; j < 4; j++)
            #pragma unroll
            for (int t = 0; t < 4; t++) acc[i][j][t] = 0.f;

    const __nv_bfloat16* Ab = A  + (size_t)row0 * Kr;
    const __nv_bfloat16* Bb = Bw + (size_t)col0 * Kr;
    int kt_total = Kr / GBK;

    auto load_stage = [&](int st, int kb) {
        __nv_bfloat16* as = As + st * GBM * PADK;
        __nv_bfloat16* bs = Bs + st * GBN * PADK;
        #pragma unroll
        for (int c = 0; c < 4; c++) {
            int idx = tid + c*256;
            int r = idx >> 3, kk = (idx & 7) * 8;
            cp16(&as[r*PADK + kk], Ab + (size_t)r*Kr + kb + kk);
            cp16(&bs[r*PADK + kk], Bb + (size_t)r*Kr + kb + kk);
        }
    };

    #pragma unroll
    for (int s = 0; s < STAGES-1; s++) {
        if (s < kt_total) load_stage(s, s*GBK);
        asm volatile("cp.async.commit_group;\n" ::: "memory");
    }

    for (int kt = 0; kt < kt_total; kt++) {
        asm volatile("cp.async.wait_group %0;\n" :: "n"(STAGES-2) : "memory");
        __syncthreads();

        int nk = kt + STAGES - 1;
        if (nk < kt_total) load_stage(nk % STAGES, nk*GBK);
        asm volatile("cp.async.commit_group;\n" ::: "memory");

        const __nv_bfloat16* as = As + (kt % STAGES) * GBM * PADK;
        const __nv_bfloat16* bs = Bs + (kt % STAGES) * GBN * PADK;

        #pragma unroll
        for (int ks = 0; ks < 4; ks++) {
            int kof = ks * 16;
            uint32_t ra[4][4];
            #pragma unroll
            for (int mi = 0; mi < 4; mi++) {
                int rr = warp_m*64 + mi*16 + (lane & 15);
                ldsm4(ra[mi], as + rr*PADK + kof + (lane >> 4)*8);
            }
            uint32_t rb[2][4];
            #pragma unroll
            for (int nj = 0; nj < 2; nj++) {
                int nn = warp_n*32 + nj*16 + (lane & 7) + ((lane & 16) >> 1);
                ldsm4(rb[nj], bs + nn*PADK + kof + ((lane >> 3) & 1)*8);
            }
            #pragma unroll
            for (int mi = 0; mi < 4; mi++)
                #pragma unroll
                for (int nt = 0; nt < 4; nt++)
                    mma16816(acc[mi][nt], ra[mi], &rb[nt >> 1][(nt & 1)*2]);
        }
    }

    #pragma unroll
    for (int mi = 0; mi < 4; mi++) {
        int rw = row0 + warp_m*64 + mi*16 + (lane >> 2);
        #pragma unroll
        for (int nt = 0; nt < 4; nt++) {
            int cw = col0 + warp_n*32 + nt*8 + (lane & 3)*2;
            float2 bb = *(const float2*)(bias + cw);
            float v0 = acc[mi][nt][0] + bb.x;
            float v1 = acc[mi][nt][1] + bb.y;
            float v2 = acc[mi][nt][2] + bb.x;
            float v3 = acc[mi][nt][3] + bb.y;
            if (mode == 0) {
                float* C = (float*)Cc;
                *(float2*)(C + (size_t)rw*Nr + cw)     = make_float2(v0, v1);
                *(float2*)(C + (size_t)(rw+8)*Nr + cw) = make_float2(v2, v3);
            } else if (mode == 1) {
                v0 = v0 * normcdff(v0); v1 = v1 * normcdff(v1);
                v2 = v2 * normcdff(v2); v3 = v3 * normcdff(v3);
                __nv_bfloat16* C = (__nv_bfloat16*)Cc;
                *(__nv_bfloat162*)(C + (size_t)rw*Nr + cw)     = __floats2bfloat162_rn(v0, v1);
                *(__nv_bfloat162*)(C + (size_t)(rw+8)*Nr + cw) = __floats2bfloat162_rn(v2, v3);
            } else if (mode == 2) {
                float* C = (float*)Cc;
                float2 r1 = *(const float2*)(res + (size_t)rw*Nr + cw);
                float2 r2 = *(const float2*)(res + (size_t)(rw+8)*Nr + cw);
                *(float2*)(C + (size_t)rw*Nr + cw)     = make_float2(v0 + r1.x, v1 + r1.y);
                *(float2*)(C + (size_t)(rw+8)*Nr + cw) = make_float2(v2 + r2.x, v3 + r2.y);
            } else {
                __nv_bfloat16* C = (__nv_bfloat16*)Cc;
                *(__nv_bfloat162*)(C + (size_t)rw*Nr + cw)     = __floats2bfloat162_rn(v0, v1);
                *(__nv_bfloat162*)(C + (size_t)(rw+8)*Nr + cw) = __floats2bfloat162_rn(v2, v3);
            }
        }
    }
}

// ---------------- MMA flash attention: 128q/block, cp.async 2-stage K/V -------
#define AQ 128
#define AKB 128
#define APAD 72
#define QBYTES (AQ * APAD * 2)          // 18432
#define KVBYTES (AKB * APAD * 2)        // 18432
#define SMEM_A (QBYTES + 4 * KVBYTES)   // 92160

__global__ __launch_bounds__(256) void attn_mma_kernel(
    const __nv_bfloat16* __restrict__ q, const __nv_bfloat16* __restrict__ k,
    const __nv_bfloat16* __restrict__ v, __nv_bfloat16* __restrict__ y)
{
    extern __shared__ __align__(16) char smraw[];
    __nv_bfloat16* Qs = (__nv_bfloat16*)smraw;                       // [128][72]
    __nv_bfloat16* KsS[2], *VsS[2];
    KsS[0] = (__nv_bfloat16*)(smraw + QBYTES);
    VsS[0] = (__nv_bfloat16*)(smraw + QBYTES + KVBYTES);
    KsS[1] = (__nv_bfloat16*)(smraw + QBYTES + 2*KVBYTES);
    VsS[1] = (__nv_bfloat16*)(smraw + QBYTES + 3*KVBYTES);

    int b = blockIdx.z, h = blockIdx.y;
    int q0 = blockIdx.x * AQ;
    int tid = threadIdx.x, wid = tid >> 5, lane = tid & 31;

    {   // Q fill (plain loads; covered by first barrier)
        int row = tid >> 1, half = (tid & 1) * 32;
        const uint4* src = (const uint4*)(q + ((size_t)(b*Sv + q0 + row))*QKVS + h*HDv + half);
        uint4* dst = (uint4*)&Qs[row*APAD + half];
        dst[0] = src[0]; dst[1] = src[1]; dst[2] = src[2]; dst[3] = src[3];
    }

    auto fill_async = [&](int st, int j0) {
        #pragma unroll
        for (int c = 0; c < 4; c++) {
            int idx = tid + c*256;
            int row = idx >> 3, col = (idx & 7) * 8;
            size_t off = ((size_t)(b*Sv + j0 + row))*QKVS + h*HDv + col;
            cp16(&KsS[st][row*APAD + col], k + off);
            cp16(&VsS[st][row*APAD + col], v + off);
        }
    };

    int ntiles = q0/AKB + 1;
    fill_async(0, 0);
    asm volatile("cp.async.commit_group;\n" ::: "memory");

    float m0 = -1e30f, m1 = -1e30f, l0 = 0.f, l1 = 0.f;
    float Oa[8][4];
    #pragma unroll
    for (int i = 0; i < 8; i++)
        #pragma unroll
        for (int j = 0; j < 4; j++) Oa[i][j] = 0.f;

    int r_lo = lane >> 2;
    int colb = (lane & 3) * 2;
    int wrow_max = q0 + wid*16 + 15;

    for (int ti = 0; ti < ntiles; ti++) {
        int j0 = ti * AKB;
        if (ti + 1 < ntiles) fill_async((ti+1) & 1, j0 + AKB);
        asm volatile("cp.async.commit_group;\n" ::: "memory");
        asm volatile("cp.async.wait_group 1;\n" ::: "memory");
        __syncthreads();

        const __nv_bfloat16* Ks = KsS[ti & 1];
        const __nv_bfloat16* Vs = VsS[ti & 1];

        #pragma unroll
        for (int sub = 0; sub < 2; sub++) {
            int jb = j0 + sub*64;
            if (jb > wrow_max) break;
            int kro = sub*64;

            float c[8][4];
            #pragma unroll
            for (int i = 0; i < 8; i++)
                #pragma unroll
                for (int j = 0; j < 4; j++) c[i][j] = 0.f;

            #pragma unroll
            for (int kk = 0; kk < 4; kk++) {
                int kof = kk * 16;
                uint32_t ra[4];
                ldsm4(ra, &Qs[(wid*16 + (lane & 15))*APAD + kof + (lane >> 4)*8]);
                #pragma unroll
                for (int nt = 0; nt < 4; nt++) {
                    uint32_t rb[4];
                    int nn = kro + nt*16 + (lane & 7) + ((lane & 16) >> 1);
                    ldsm4(rb, &Ks[nn*APAD + kof + ((lane >> 3) & 1)*8]);
                    mma16816(c[2*nt],   ra, &rb[0]);
                    mma16816(c[2*nt+1], ra, &rb[2]);
                }
            }

            int row0 = q0 + wid*16 + r_lo;
            int row1 = row0 + 8;
            #pragma unroll
            for (int nt = 0; nt < 8; nt++) {
                c[nt][0] *= 0.125f; c[nt][1] *= 0.125f;
                c[nt][2] *= 0.125f; c[nt][3] *= 0.125f;
            }
            if (jb + 63 > row0) {
                #pragma unroll
                for (int nt = 0; nt < 8; nt++) {
                    int col = jb + nt*8 + colb;
                    if (col   > row0) c[nt][0] = -1e30f;
                    if (col+1 > row0) c[nt][1] = -1e30f;
                    if (col   > row1) c[nt][2] = -1e30f;
                    if (col+1 > row1) c[nt][3] = -1e30f;
                }
            }

            float rm0 = -1e30f, rm1 = -1e30f;
            #pragma unroll
            for (int nt = 0; nt < 8; nt++) {
                rm0 = fmaxf(rm0, fmaxf(c[nt][0], c[nt][1]));
                rm1 = fmaxf(rm1, fmaxf(c[nt][2], c[nt][3]));
            }
            rm0 = fmaxf(rm0, __shfl_xor_sync(0xffffffffu, rm0, 1));
            rm0 = fmaxf(rm0, __shfl_xor_sync(0xffffffffu, rm0, 2));
            rm1 = fmaxf(rm1, __shfl_xor_sync(0xffffffffu, rm1, 1));
            rm1 = fmaxf(rm1, __shfl_xor_sync(0xffffffffu, rm1, 2));

            float mn0 = fmaxf(m0, rm0), mn1 = fmaxf(m1, rm1);
            float cr0 = __expf(m0 - mn0), cr1 = __expf(m1 - mn1);
            m0 = mn0; m1 = mn1;

            float ps0 = 0.f, ps1 = 0.f;
            #pragma unroll
            for (int nt = 0; nt < 8; nt++) {
                c[nt][0] = __expf(c[nt][0] - mn0);
                c[nt][1] = __expf(c[nt][1] - mn0);
                c[nt][2] = __expf(c[nt][2] - mn1);
                c[nt][3] = __expf(c[nt][3] - mn1);
                ps0 += c[nt][0] + c[nt][1];
                ps1 += c[nt][2] + c[nt][3];
            }
            ps0 += __shfl_xor_sync(0xffffffffu, ps0, 1);
            ps0 += __shfl_xor_sync(0xffffffffu, ps0, 2);
            ps1 += __shfl_xor_sync(0xffffffffu, ps1, 1);
            ps1 += __shfl_xor_sync(0xffffffffu, ps1, 2);
            l0 = l0*cr0 + ps0;
            l1 = l1*cr1 + ps1;

            #pragma unroll
            for (int nt = 0; nt < 8; nt++) {
                Oa[nt][0] *= cr0; Oa[nt][1] *= cr0;
                Oa[nt][2] *= cr1; Oa[nt][3] *= cr1;
            }

            #pragma unroll
            for (int kt = 0; kt < 4; kt++) {
                uint32_t a[4];
                __nv_bfloat162 p0 = __floats2bfloat162_rn(c[2*kt][0],   c[2*kt][1]);
                __nv_bfloat162 p1 = __floats2bfloat162_rn(c[2*kt][2],   c[2*kt][3]);
                __nv_bfloat162 p2 = __floats2bfloat162_rn(c[2*kt+1][0], c[2*kt+1][1]);
                __nv_bfloat162 p3 = __floats2bfloat162_rn(c[2*kt+1][2], c[2*kt+1][3]);
                a[0] = *(uint32_t*)&p0; a[1] = *(uint32_t*)&p1;
                a[2] = *(uint32_t*)&p2; a[3] = *(uint32_t*)&p3;
                #pragma unroll
                for (int nt = 0; nt < 4; nt++) {
                    uint32_t rv[4];
                    int key = kro + kt*16 + (lane & 7) + ((lane >> 3) & 1)*8;
                    int dim = nt*16 + (lane >> 4)*8;
                    ldsm4t(rv, &Vs[key*APAD + dim]);
                    mma16816(Oa[2*nt],   a, &rv[0]);
                    mma16816(Oa[2*nt+1], a, &rv[2]);
                }
            }
        }
        __syncthreads();   // stage (ti+1)&1 is refilled next iter; ensure all warps done
    }

    float il0 = 1.0f / l0, il1 = 1.0f / l1;
    int grow0 = q0 + wid*16 + r_lo;
    #pragma unroll
    for (int nt = 0; nt < 8; nt++) {
        int dcol = nt*8 + colb;
        __nv_bfloat16* yp0 = y + ((size_t)(b*Sv + grow0))*Dv + h*HDv + dcol;
        __nv_bfloat16* yp1 = y + ((size_t)(b*Sv + grow0 + 8))*Dv + h*HDv + dcol;
        *(__nv_bfloat162*)yp0 = __floats2bfloat162_rn(Oa[nt][0]*il0, Oa[nt][1]*il0);
        *(__nv_bfloat162*)yp1 = __floats2bfloat162_rn(Oa[nt][2]*il1, Oa[nt][3]*il1);
    }
}

// ---------------- final loss (bf16 logits, single-pass online softmax) --------
__global__ __launch_bounds__(256) void loss_kernel(const __nv_bfloat16* __restrict__ logits,
                                                   const int* __restrict__ tokens,
                                                   float* __restrict__ out)
{
    __shared__ float smax[8], ssum[8];
    int row = blockIdx.x, tid = threadIdx.x;
    const uint4* lr8 = (const uint4*)(logits + (size_t)row * Cv);

    float m = -1e30f, s = 0.f;
    #pragma unroll
    for (int c = 0; c < Cv/2048; c++) {
        uint4 u = lr8[tid + c*256];
        float2 f0 = __bfloat1622float2(*(__nv_bfloat162*)&u.x);
        float2 f1 = __bfloat1622float2(*(__nv_bfloat162*)&u.y);
        float2 f2 = __bfloat1622float2(*(__nv_bfloat162*)&u.z);
        float2 f3 = __bfloat1622float2(*(__nv_bfloat162*)&u.w);
        float vm = fmaxf(fmaxf(fmaxf(f0.x, f0.y), fmaxf(f1.x, f1.y)),
                         fmaxf(fmaxf(f2.x, f2.y), fmaxf(f3.x, f3.y)));
        if (vm > m) { s = s * __expf(m - vm); m = vm; }
        s += __expf(f0.x - m) + __expf(f0.y - m) + __expf(f1.x - m) + __expf(f1.y - m)
           + __expf(f2.x - m) + __expf(f2.y - m) + __expf(f3.x - m) + __expf(f3.y - m);
    }
    #pragma unroll
    for (int o = 16; o; o >>= 1) {
        float m2 = __shfl_xor_sync(0xffffffffu, m, o);
        float s2 = __shfl_xor_sync(0xffffffffu, s, o);
        float mn = fmaxf(m, m2);
        s = s * __expf(m - mn) + s2 * __expf(m2 - mn);
        m = mn;
    }
    int w = tid >> 5;
    if ((tid & 31) == 0) { smax[w] = m; ssum[w] = s; }
    __syncthreads();
    if (tid == 0) {
        m = smax[0]; s = ssum[0];
        #pragma unroll
        for (int i = 1; i < 8; i++) {
            float mn = fmaxf(m, smax[i]);
            s = s * __expf(m - mn) + ssum[i] * __expf(smax[i] - mn);
            m = mn;
        }
        int t = tokens[row];
        if (t != PADTOK) {
            float lt = __bfloat162float(logits[(size_t)row * Cv + t]);
            float lp = lt - m - logf(s);
            atomicAdd(&out[row / Sv], lp);
        }
    }
}

// ---------------- driver -----------------------------------------------------
static void run_hgemm(const __nv_bfloat16* A, const __nv_bfloat16* W,
                      const float* bias, const float* res,
                      void* Cc, int M_, int N_, int K_, int mode)
{
    dim3 grid(N_/GBN, M_/GBM);
    hgemm_kernel<<<grid, 256, SMEM_G>>>(A, W, bias, res, Cc, M_, N_, K_, mode);
}

extern "C" void kernel_launch(void* const* d_in, const int* in_sizes, int n_in,
                              void* d_out, int out_size)
{
    const int*   tokens = (const int*)  d_in[0];
    const float* emb    = (const float*)d_in[1];
    const float* pe     = (const float*)d_in[2];
    const float* ln1_g  = (const float*)d_in[3];
    const float* ln1_b  = (const float*)d_in[4];
    const float* Wq     = (const float*)d_in[5];
    const float* bq     = (const float*)d_in[6];
    const float* Wk     = (const float*)d_in[7];
    const float* bk     = (const float*)d_in[8];
    const float* Wv     = (const float*)d_in[9];
    const float* bv     = (const float*)d_in[10];
    const float* Wo     = (const float*)d_in[11];
    const float* bo     = (const float*)d_in[12];
    const float* ln2_g  = (const float*)d_in[13];
    const float* ln2_b  = (const float*)d_in[14];
    const float* W1     = (const float*)d_in[15];
    const float* b1     = (const float*)d_in[16];
    const float* W2     = (const float*)d_in[17];
    const float* b2     = (const float*)d_in[18];
    const float* lnf_g  = (const float*)d_in[19];
    const float* lnf_b  = (const float*)d_in[20];
    const float* fcW    = (const float*)d_in[21];
    const float* fcb    = (const float*)d_in[22];
    float* out = (float*)d_out;

    cudaFuncSetAttribute(hgemm_kernel, cudaFuncAttributeMaxDynamicSharedMemorySize, SMEM_G);
    cudaFuncSetAttribute(attn_mma_kernel, cudaFuncAttributeMaxDynamicSharedMemorySize, SMEM_A);

    float *x, *bqkv;
    __nv_bfloat16 *h, *y, *ff, *qkv, *logits;
    __nv_bfloat16 *wqkv, *wo_b, *w1_b, *w2_b, *fcw_b;
    cudaGetSymbolAddress((void**)&x,    g_x);
    cudaGetSymbolAddress((void**)&h,    g_h);
    cudaGetSymbolAddress((void**)&qkv,  g_qkv);
    cudaGetSymbolAddress((void**)&y,    g_y);
    cudaGetSymbolAddress((void**)&ff,   g_ff);
    cudaGetSymbolAddress((void**)&logits, g_logits);
    cudaGetSymbolAddress((void**)&wqkv, g_Wqkv);
    cudaGetSymbolAddress((void**)&bqkv, g_bqkv);
    cudaGetSymbolAddress((void**)&wo_b, g_Wo);
    cudaGetSymbolAddress((void**)&w1_b, g_W1);
    cudaGetSymbolAddress((void**)&w2_b, g_W2);
    cudaGetSymbolAddress((void**)&fcw_b, g_fcW);

    conv_all_kernel<<<(unsigned)((NTOTAL + 255)/256), 256>>>(
        (const float4*)Wq, (const float4*)Wk, (const float4*)Wv,
        (const float4*)Wo, (const float4*)W1, (const float4*)W2, (const float4*)fcW,
        (const float4*)bq, (const float4*)bk, (const float4*)bv, (float4*)bqkv,
        (__nv_bfloat162*)wqkv, (__nv_bfloat162*)wo_b,
        (__nv_bfloat162*)w1_b, (__nv_bfloat162*)w2_b, (__nv_bfloat162*)fcw_b);
    embed_kernel<<<(Mv*Dv/4 + 255)/256, 256>>>(tokens, (const float4*)emb,
                                               (const float4*)pe, (float4*)x, out);

    for (int i = 0; i < Lv; i++) {
        const __nv_bfloat16* wl  = wqkv + (size_t)i*QKVS*Dv;
        const float*         bl  = bqkv + (size_t)i*QKVS;
        const __nv_bfloat16* wo  = wo_b + (size_t)i*Dv*Dv;
        const __nv_bfloat16* w1  = w1_b + (size_t)i*FFv*Dv;
        const __nv_bfloat16* w2  = w2_b + (size_t)i*Dv*FFv;

        ln_kernel<<<Mv/8, 256>>>(x, ln1_g + i*Dv, ln1_b + i*Dv, h);
        run_hgemm(h, wl, bl, nullptr, qkv, Mv, QKVS, Dv, 3);

        dim3 agrid(Sv/AQ, Hv, Bv);
        attn_mma_kernel<<<agrid, 256, SMEM_A>>>(qkv, qkv + Dv, qkv + 2*Dv, y);

        run_hgemm(y, wo, bo + i*Dv, x, x, Mv, Dv, Dv, 2);

        ln_kernel<<<Mv/8, 256>>>(x, ln2_g + i*Dv, ln2_b + i*Dv, h);
        run_hgemm(h, w1, b1 + i*FFv, nullptr, ff, Mv, FFv, Dv, 1);
        run_hgemm(ff, w2, b2 + i*Dv, x, x, Mv, Dv, FFv, 2);
    }

    ln_kernel<<<Mv/8, 256>>>(x, lnf_g, lnf_b, h);
    run_hgemm(h, fcw_b, fcb, nullptr, logits, Mv, Cv, Dv, 3);

    loss_kernel<<<Mv, 256>>>(logits, tokens, out);
}